// round 1
// baseline (speedup 1.0000x reference)
#include <cuda_runtime.h>
#include <cuda_bf16.h>

#define DIM     640
#define HEADS   10
#define HD      64
#define B_SZ    16
#define SEQ     1024
#define M_TOT   (B_SZ * SEQ)     // 16384
#define QKV_N   (3 * DIM)        // 1920
#define ATT_SCALE 0.0395284707521047416f   // 640^-0.5  (reference uses DIM, not HEAD_DIM)

// ---------------- scratch (device globals: allocation-free) ----------------
__device__ float g_q[B_SZ * HEADS * SEQ * HD];   // [B][H][N][64]
__device__ float g_k[B_SZ * HEADS * SEQ * HD];
__device__ float g_v[B_SZ * HEADS * SEQ * HD];
__device__ float g_att[M_TOT * DIM];             // [B][N][DIM]

// ---------------- SGEMM: C[M,N] = A[M,K] @ W[K,N] + bias ----------------
// 128x128 block tile, BK=16, 256 threads, 8x8 per thread.
// QKV_SCATTER: epilogue scatters columns into g_q / g_k / g_v instead of C.
template <bool QKV_SCATTER>
__global__ __launch_bounds__(256)
void sgemm_kernel(const float* __restrict__ A, const float* __restrict__ W,
                  const float* __restrict__ bias, float* __restrict__ C,
                  int M, int N, int K)
{
    __shared__ float As[16][128];   // [k][m]
    __shared__ float Bs[16][128];   // [k][n]

    const int tid = threadIdx.x;
    const int m0  = blockIdx.y * 128;
    const int n0  = blockIdx.x * 128;
    const int tx  = tid & 15;       // 0..15 -> 8 cols each
    const int ty  = tid >> 4;       // 0..15 -> 8 rows each

    // A-load mapping: 512 float4 per tile, 2 per thread
    const int arow = tid >> 2;            // 0..63
    const int acol = (tid & 3) << 2;      // 0,4,8,12

    float acc[8][8];
    #pragma unroll
    for (int i = 0; i < 8; ++i)
        #pragma unroll
        for (int j = 0; j < 8; ++j) acc[i][j] = 0.f;

    for (int k0 = 0; k0 < K; k0 += 16) {
        // load A tile (transposed into As[k][m])
        #pragma unroll
        for (int r = 0; r < 2; ++r) {
            int row = arow + r * 64;
            float4 v = *(const float4*)&A[(size_t)(m0 + row) * K + k0 + acol];
            As[acol + 0][row] = v.x;
            As[acol + 1][row] = v.y;
            As[acol + 2][row] = v.z;
            As[acol + 3][row] = v.w;
        }
        // load B tile (direct)
        #pragma unroll
        for (int r = 0; r < 2; ++r) {
            int idx  = tid + r * 256;          // 0..511
            int brow = idx >> 5;               // 0..15
            int bcol = (idx & 31) << 2;        // 0..124
            *(float4*)&Bs[brow][bcol] =
                *(const float4*)&W[(size_t)(k0 + brow) * N + n0 + bcol];
        }
        __syncthreads();

        #pragma unroll
        for (int k = 0; k < 16; ++k) {
            float a[8], b[8];
            #pragma unroll
            for (int i = 0; i < 8; ++i) a[i] = As[k][ty * 8 + i];
            #pragma unroll
            for (int j = 0; j < 8; ++j) b[j] = Bs[k][tx * 8 + j];
            #pragma unroll
            for (int i = 0; i < 8; ++i)
                #pragma unroll
                for (int j = 0; j < 8; ++j)
                    acc[i][j] += a[i] * b[j];
        }
        __syncthreads();
    }

    // epilogue
    if (!QKV_SCATTER) {
        #pragma unroll
        for (int i = 0; i < 8; ++i) {
            int row = m0 + ty * 8 + i;
            #pragma unroll
            for (int j = 0; j < 8; ++j) {
                int n = n0 + tx * 8 + j;
                C[(size_t)row * N + n] = acc[i][j] + bias[n];
            }
        }
    } else {
        #pragma unroll
        for (int i = 0; i < 8; ++i) {
            int mg = m0 + ty * 8 + i;
            int b  = mg >> 10;           // /1024
            int iq = mg & 1023;
            #pragma unroll
            for (int j = 0; j < 8; ++j) {
                int n = n0 + tx * 8 + j;
                float val = acc[i][j] + bias[n];
                int sel = n / DIM;       // 0=q 1=k 2=v
                int c   = n - sel * DIM;
                int h   = c >> 6;        // /64
                int d   = c & 63;
                float* dst = (sel == 0) ? g_q : (sel == 1) ? g_k : g_v;
                dst[(((size_t)(b * HEADS + h)) * SEQ + iq) * HD + d] = val;
            }
        }
    }
}

// ---------------- flash attention: 1 thread = 1 query row ----------------
// grid: (SEQ/128, B*H), block: 128 threads. K/V tiles of 64 keys in smem.
__global__ __launch_bounds__(128)
void flash_kernel()
{
    __shared__ float Ks[64][HD];
    __shared__ float Vs[64][HD];

    const int bh  = blockIdx.y;                      // 0..159
    const int row = blockIdx.x * 128 + threadIdx.x;  // query row within seq

    const float* qptr = g_q + ((size_t)bh * SEQ + row) * HD;
    float q[64];
    #pragma unroll
    for (int i = 0; i < 16; ++i) {
        float4 v = *(const float4*)&qptr[i * 4];
        q[i*4+0] = v.x; q[i*4+1] = v.y; q[i*4+2] = v.z; q[i*4+3] = v.w;
    }

    float o[64];
    #pragma unroll
    for (int d = 0; d < 64; ++d) o[d] = 0.f;
    float m = -1e30f, l = 0.f;

    const float4* kbase = (const float4*)(g_k + (size_t)bh * SEQ * HD);
    const float4* vbase = (const float4*)(g_v + (size_t)bh * SEQ * HD);
    float4* ks4 = (float4*)&Ks[0][0];
    float4* vs4 = (float4*)&Vs[0][0];

    for (int kt = 0; kt < SEQ; kt += 64) {
        __syncthreads();
        // cooperative load of 64x64 K and V tiles (coalesced float4)
        const float4* kg = kbase + (size_t)kt * (HD / 4);
        const float4* vg = vbase + (size_t)kt * (HD / 4);
        #pragma unroll
        for (int r = 0; r < 8; ++r) {
            int idx = threadIdx.x + r * 128;
            ks4[idx] = kg[idx];
            vs4[idx] = vg[idx];
        }
        __syncthreads();

        #pragma unroll 2
        for (int j = 0; j < 64; ++j) {
            const float4* kr = (const float4*)&Ks[j][0];
            float s = 0.f;
            #pragma unroll
            for (int i = 0; i < 16; ++i) {
                float4 kv = kr[i];
                s += q[i*4+0]*kv.x + q[i*4+1]*kv.y + q[i*4+2]*kv.z + q[i*4+3]*kv.w;
            }
            s *= ATT_SCALE;

            float p;
            if (s > m) {                       // rare: ~ln(1024) times per row
                float corr = __expf(m - s);
                l *= corr;
                #pragma unroll
                for (int d = 0; d < 64; ++d) o[d] *= corr;
                m = s;
                p = 1.f;
            } else {
                p = __expf(s - m);
            }
            l += p;

            const float4* vr = (const float4*)&Vs[j][0];
            #pragma unroll
            for (int i = 0; i < 16; ++i) {
                float4 vv = vr[i];
                o[i*4+0] += p * vv.x;
                o[i*4+1] += p * vv.y;
                o[i*4+2] += p * vv.z;
                o[i*4+3] += p * vv.w;
            }
        }
    }

    const float inv = 1.f / l;
    const int b = bh / HEADS;
    const int h = bh - b * HEADS;
    float* op = g_att + ((size_t)(b * SEQ + row)) * DIM + h * HD;
    #pragma unroll
    for (int i = 0; i < 16; ++i) {
        float4 v = make_float4(o[i*4+0]*inv, o[i*4+1]*inv, o[i*4+2]*inv, o[i*4+3]*inv);
        *(float4*)&op[i * 4] = v;
    }
}

// ---------------- launch ----------------
extern "C" void kernel_launch(void* const* d_in, const int* in_sizes, int n_in,
                              void* d_out, int out_size)
{
    const float* x     = (const float*)d_in[0];
    const float* w_qkv = (const float*)d_in[1];
    const float* b_qkv = (const float*)d_in[2];
    const float* w_out = (const float*)d_in[3];
    const float* b_out = (const float*)d_in[4];
    float* out = (float*)d_out;

    // 1) QKV GEMM + scatter into g_q/g_k/g_v
    sgemm_kernel<true><<<dim3(QKV_N / 128, M_TOT / 128), 256>>>(
        x, w_qkv, b_qkv, nullptr, M_TOT, QKV_N, DIM);

    // 2) flash attention -> g_att [B,N,DIM]
    flash_kernel<<<dim3(SEQ / 128, B_SZ * HEADS), 128>>>();

    // 3) out projection -> d_out
    float* attp = nullptr;
    cudaGetSymbolAddress((void**)&attp, g_att);
    sgemm_kernel<false><<<dim3(DIM / 128, M_TOT / 128), 256>>>(
        attp, w_out, b_out, out, M_TOT, DIM, DIM);
}

// round 3
// speedup vs baseline: 1.3866x; 1.3866x over previous
#include <cuda_runtime.h>
#include <cuda_bf16.h>
#include <cstdint>

#define DIM     640
#define HEADS   10
#define HD      64
#define B_SZ    16
#define SEQ     1024
#define M_TOT   (B_SZ * SEQ)     // 16384
#define QKV_N   (3 * DIM)        // 1920
#define ATT_SCALE 0.0395284707521047416f   // 640^-0.5

// ---------------- scratch (device globals) ----------------
__device__ __nv_bfloat16 g_xh[(size_t)M_TOT * DIM];
__device__ __nv_bfloat16 g_xl[(size_t)M_TOT * DIM];
__device__ __nv_bfloat16 g_wqh[(size_t)QKV_N * DIM];   // w_qkv^T hi  [1920][640]
__device__ __nv_bfloat16 g_wql[(size_t)QKV_N * DIM];
__device__ __nv_bfloat16 g_woh[(size_t)DIM * DIM];     // w_out^T hi  [640][640]
__device__ __nv_bfloat16 g_wol[(size_t)DIM * DIM];
__device__ float g_q[(size_t)B_SZ * HEADS * SEQ * HD];
__device__ float g_k[(size_t)B_SZ * HEADS * SEQ * HD];
__device__ float g_v[(size_t)B_SZ * HEADS * SEQ * HD];
__device__ __nv_bfloat16 g_ah[(size_t)M_TOT * DIM];    // attention out hi (bf16 split)
__device__ __nv_bfloat16 g_al[(size_t)M_TOT * DIM];

// ---------------- helpers ----------------
__device__ __forceinline__ uint32_t smem_u32(const void* p) {
    uint32_t a;
    asm("{ .reg .u64 t; cvta.to.shared.u64 t, %1; cvt.u32.u64 %0, t; }"
        : "=r"(a) : "l"(p));
    return a;
}

__device__ __forceinline__ void ldmatrix_x4(uint32_t* r, uint32_t addr) {
    asm volatile("ldmatrix.sync.aligned.m8n8.x4.shared.b16 {%0,%1,%2,%3}, [%4];"
                 : "=r"(r[0]), "=r"(r[1]), "=r"(r[2]), "=r"(r[3]) : "r"(addr));
}
__device__ __forceinline__ void ldmatrix_x2(uint32_t* r, uint32_t addr) {
    asm volatile("ldmatrix.sync.aligned.m8n8.x2.shared.b16 {%0,%1}, [%2];"
                 : "=r"(r[0]), "=r"(r[1]) : "r"(addr));
}
__device__ __forceinline__ void mma_bf16(float* c, const uint32_t* a, const uint32_t* b) {
    asm volatile("mma.sync.aligned.m16n8k16.row.col.f32.bf16.bf16.f32 "
                 "{%0,%1,%2,%3}, {%4,%5,%6,%7}, {%8,%9}, {%0,%1,%2,%3};"
                 : "+f"(c[0]), "+f"(c[1]), "+f"(c[2]), "+f"(c[3])
                 : "r"(a[0]), "r"(a[1]), "r"(a[2]), "r"(a[3]), "r"(b[0]), "r"(b[1]));
}

// smem tile layout: 128 rows x 32 bf16 (64B/row); 16B chunks swizzled:
// byte_off(row, chunk) = row*64 + 16*(chunk ^ ((row>>1)&3))
__device__ __forceinline__ uint32_t tile_off(int row, int chunk) {
    return (uint32_t)(row * 64 + 16 * (chunk ^ ((row >> 1) & 3)));
}

// ---------------- conversion kernels ----------------
__global__ void split_f32(const float* __restrict__ in,
                          __nv_bfloat16* __restrict__ hi,
                          __nv_bfloat16* __restrict__ lo, int n)
{
    int i = blockIdx.x * 256 + threadIdx.x;
    if (i < n) {
        float v = in[i];
        __nv_bfloat16 h = __float2bfloat16(v);
        hi[i] = h;
        lo[i] = __float2bfloat16(v - __bfloat162float(h));
    }
}

// w[K][N] fp32 -> wT hi/lo [N][K] bf16
__global__ void splitT_f32(const float* __restrict__ w,
                           __nv_bfloat16* __restrict__ hiT,
                           __nv_bfloat16* __restrict__ loT, int K, int N)
{
    int i = blockIdx.x * 256 + threadIdx.x;
    if (i < K * N) {
        int k = i / N, n = i - k * N;
        float v = w[i];
        __nv_bfloat16 h = __float2bfloat16(v);
        hiT[(size_t)n * K + k] = h;
        loT[(size_t)n * K + k] = __float2bfloat16(v - __bfloat162float(h));
    }
}

// ---------------- mma.sync split-bf16 GEMM ----------------
// C[M,N] = A[M,K] @ B^T[N,K] + bias.  A hi/lo [M][K], B hi/lo [N][K].
// CTA tile 128x128, BK=32, 8 warps (2x4), warp tile 64x32.
template <bool QKV>
__global__ __launch_bounds__(256, 2)
void gemm_mma(const __nv_bfloat16* __restrict__ Ah, const __nv_bfloat16* __restrict__ Al,
              const __nv_bfloat16* __restrict__ Bh, const __nv_bfloat16* __restrict__ Bl,
              const float* __restrict__ bias, float* __restrict__ Cout,
              int Ntot, int Ktot)
{
    __shared__ __nv_bfloat16 sAh[128 * 32], sAl[128 * 32];
    __shared__ __nv_bfloat16 sBh[128 * 32], sBl[128 * 32];

    const int tid  = threadIdx.x;
    const int lane = tid & 31;
    const int wid  = tid >> 5;
    const int wm   = wid >> 2;          // 0..1
    const int wn   = wid & 3;           // 0..3
    const int m0   = blockIdx.y * 128;
    const int n0   = blockIdx.x * 128;

    const uint32_t aAh = smem_u32(sAh), aAl = smem_u32(sAl);
    const uint32_t aBh = smem_u32(sBh), aBl = smem_u32(sBl);

    float c[4][4][4];
    #pragma unroll
    for (int i = 0; i < 4; ++i)
        #pragma unroll
        for (int j = 0; j < 4; ++j)
            #pragma unroll
            for (int t = 0; t < 4; ++t) c[i][j][t] = 0.f;

    for (int k0 = 0; k0 < Ktot; k0 += 32) {
        // load 4 tiles: 512 x 16B chunks each, 2 per thread per tile
        #pragma unroll
        for (int it = 0; it < 2; ++it) {
            const int idx = it * 256 + tid;
            const int row = idx >> 2;
            const int cc  = idx & 3;
            const uint32_t so = tile_off(row, cc);
            const size_t ga = (size_t)(m0 + row) * Ktot + k0 + cc * 8;
            const size_t gb = (size_t)(n0 + row) * Ktot + k0 + cc * 8;
            *(uint4*)((char*)sAh + so) = *(const uint4*)(Ah + ga);
            *(uint4*)((char*)sAl + so) = *(const uint4*)(Al + ga);
            *(uint4*)((char*)sBh + so) = *(const uint4*)(Bh + gb);
            *(uint4*)((char*)sBl + so) = *(const uint4*)(Bl + gb);
        }
        __syncthreads();

        #pragma unroll
        for (int ks = 0; ks < 2; ++ks) {
            // B fragments (k16 x n8 each), hi & lo
            uint32_t bh[4][2], bl[4][2];
            const int lr = lane & 7;
            const int lc = (lane >> 3) & 1;
            #pragma unroll
            for (int ni = 0; ni < 4; ++ni) {
                const int r = wn * 32 + ni * 8 + lr;
                const uint32_t off = tile_off(r, ks * 2 + lc);
                ldmatrix_x2(bh[ni], aBh + off);
                ldmatrix_x2(bl[ni], aBl + off);
            }
            // A fragments per mi, then 3-product mma
            #pragma unroll
            for (int mi = 0; mi < 4; ++mi) {
                uint32_t ah[4], al[4];
                const int r = wm * 64 + mi * 16 + (lane & 15);
                const uint32_t off = tile_off(r, ks * 2 + (lane >> 4));
                ldmatrix_x4(ah, aAh + off);
                ldmatrix_x4(al, aAl + off);
                #pragma unroll
                for (int ni = 0; ni < 4; ++ni) {
                    mma_bf16(c[mi][ni], ah, bh[ni]);
                    mma_bf16(c[mi][ni], ah, bl[ni]);
                    mma_bf16(c[mi][ni], al, bh[ni]);
                }
            }
        }
        __syncthreads();
    }

    // epilogue: c-frag (mi,ni): rows r, r+8 ; cols col, col+1
    #pragma unroll
    for (int mi = 0; mi < 4; ++mi) {
        #pragma unroll
        for (int ni = 0; ni < 4; ++ni) {
            const int r0  = m0 + wm * 64 + mi * 16 + (lane >> 2);
            const int col = n0 + wn * 32 + ni * 8 + (lane & 3) * 2;
            const float b0 = bias[col], b1 = bias[col + 1];
            #pragma unroll
            for (int half = 0; half < 2; ++half) {
                const int r = r0 + half * 8;
                float2 v;
                v.x = c[mi][ni][half * 2 + 0] + b0;
                v.y = c[mi][ni][half * 2 + 1] + b1;
                if (QKV) {
                    const int bb  = r >> 10;
                    const int iq  = r & 1023;
                    const int sel = col / DIM;
                    const int nc  = col - sel * DIM;
                    const int h   = nc >> 6;
                    const int d   = nc & 63;
                    float* dst = (sel == 0) ? g_q : (sel == 1) ? g_k : g_v;
                    *(float2*)&dst[(((size_t)(bb * HEADS + h)) * SEQ + iq) * HD + d] = v;
                } else {
                    *(float2*)&Cout[(size_t)r * Ntot + col] = v;
                }
            }
        }
    }
}

// ---------------- flash attention: 1 thread = 1 query row (ILP-fixed) ----------------
__global__ __launch_bounds__(128)
void flash_kernel()
{
    __shared__ float Ks[64][HD];
    __shared__ float Vs[64][HD];

    const int bh  = blockIdx.y;
    const int row = blockIdx.x * 128 + threadIdx.x;

    const float* qptr = g_q + ((size_t)bh * SEQ + row) * HD;
    float4 q[16];
    #pragma unroll
    for (int i = 0; i < 16; ++i) q[i] = *(const float4*)&qptr[i * 4];

    float o[64];
    #pragma unroll
    for (int d = 0; d < 64; ++d) o[d] = 0.f;
    float m = -1e30f, l = 0.f;

    const float4* kbase = (const float4*)(g_k + (size_t)bh * SEQ * HD);
    const float4* vbase = (const float4*)(g_v + (size_t)bh * SEQ * HD);
    float4* ks4 = (float4*)&Ks[0][0];
    float4* vs4 = (float4*)&Vs[0][0];

    for (int kt = 0; kt < SEQ; kt += 64) {
        __syncthreads();
        const float4* kg = kbase + (size_t)kt * (HD / 4);
        const float4* vg = vbase + (size_t)kt * (HD / 4);
        #pragma unroll
        for (int r = 0; r < 8; ++r) {
            int idx = threadIdx.x + r * 128;
            ks4[idx] = kg[idx];
            vs4[idx] = vg[idx];
        }
        __syncthreads();

        #pragma unroll 2
        for (int j = 0; j < 64; ++j) {
            const float4* kr = (const float4*)&Ks[j][0];
            // 4 independent accumulator chains (16 deep each)
            float s0 = 0.f, s1 = 0.f, s2 = 0.f, s3 = 0.f;
            #pragma unroll
            for (int i = 0; i < 16; ++i) {
                float4 kv = kr[i];
                s0 = fmaf(q[i].x, kv.x, s0);
                s1 = fmaf(q[i].y, kv.y, s1);
                s2 = fmaf(q[i].z, kv.z, s2);
                s3 = fmaf(q[i].w, kv.w, s3);
            }
            float s = ((s0 + s1) + (s2 + s3)) * ATT_SCALE;

            float p;
            if (s > m) {                     // rare (~ln(SEQ) per row)
                float corr = __expf(m - s);
                l *= corr;
                #pragma unroll
                for (int d = 0; d < 64; ++d) o[d] *= corr;
                m = s;
                p = 1.f;
            } else {
                p = __expf(s - m);
            }
            l += p;

            const float4* vr = (const float4*)&Vs[j][0];
            #pragma unroll
            for (int i = 0; i < 16; ++i) {
                float4 vv = vr[i];
                o[i*4+0] = fmaf(p, vv.x, o[i*4+0]);
                o[i*4+1] = fmaf(p, vv.y, o[i*4+1]);
                o[i*4+2] = fmaf(p, vv.z, o[i*4+2]);
                o[i*4+3] = fmaf(p, vv.w, o[i*4+3]);
            }
        }
    }

    const float inv = 1.f / l;
    const int b = bh / HEADS;
    const int h = bh - b * HEADS;
    const size_t base = ((size_t)(b * SEQ + row)) * DIM + h * HD;
    __nv_bfloat16* ph = g_ah + base;
    __nv_bfloat16* pl = g_al + base;
    #pragma unroll
    for (int i = 0; i < 64; i += 8) {
        __nv_bfloat16 hbuf[8], lbuf[8];
        #pragma unroll
        for (int j = 0; j < 8; ++j) {
            float v = o[i + j] * inv;
            __nv_bfloat16 hh = __float2bfloat16(v);
            hbuf[j] = hh;
            lbuf[j] = __float2bfloat16(v - __bfloat162float(hh));
        }
        *(uint4*)(ph + i) = *(const uint4*)hbuf;
        *(uint4*)(pl + i) = *(const uint4*)lbuf;
    }
}

// ---------------- launch ----------------
extern "C" void kernel_launch(void* const* d_in, const int* in_sizes, int n_in,
                              void* d_out, int out_size)
{
    const float* x     = (const float*)d_in[0];
    const float* w_qkv = (const float*)d_in[1];
    const float* b_qkv = (const float*)d_in[2];
    const float* w_out = (const float*)d_in[3];
    const float* b_out = (const float*)d_in[4];
    float* out = (float*)d_out;

    __nv_bfloat16 *xh, *xl, *wqh, *wql, *woh, *wol, *ah, *al;
    cudaGetSymbolAddress((void**)&xh,  g_xh);
    cudaGetSymbolAddress((void**)&xl,  g_xl);
    cudaGetSymbolAddress((void**)&wqh, g_wqh);
    cudaGetSymbolAddress((void**)&wql, g_wql);
    cudaGetSymbolAddress((void**)&woh, g_woh);
    cudaGetSymbolAddress((void**)&wol, g_wol);
    cudaGetSymbolAddress((void**)&ah,  g_ah);
    cudaGetSymbolAddress((void**)&al,  g_al);

    // 0) fp32 -> bf16 hi/lo splits
    const int nx = M_TOT * DIM;
    split_f32<<<(nx + 255) / 256, 256>>>(x, xh, xl, nx);
    splitT_f32<<<(DIM * QKV_N + 255) / 256, 256>>>(w_qkv, wqh, wql, DIM, QKV_N);
    splitT_f32<<<(DIM * DIM + 255) / 256, 256>>>(w_out, woh, wol, DIM, DIM);

    // 1) QKV GEMM (HMMA tensor path) + scatter into g_q/g_k/g_v
    gemm_mma<true><<<dim3(QKV_N / 128, M_TOT / 128), 256>>>(
        xh, xl, wqh, wql, b_qkv, nullptr, QKV_N, DIM);

    // 2) flash attention -> g_ah/g_al (bf16 split)
    flash_kernel<<<dim3(SEQ / 128, B_SZ * HEADS), 128>>>();

    // 3) out projection (HMMA) -> d_out
    gemm_mma<false><<<dim3(DIM / 128, M_TOT / 128), 256>>>(
        ah, al, woh, wol, b_out, out, DIM, DIM);
}

// round 4
// speedup vs baseline: 3.0183x; 2.1767x over previous
#include <cuda_runtime.h>
#include <cuda_bf16.h>
#include <cstdint>

#define DIM     640
#define HEADS   10
#define HD      64
#define B_SZ    16
#define SEQ     1024
#define M_TOT   (B_SZ * SEQ)     // 16384
#define QKV_N   (3 * DIM)        // 1920
#define ATT_SCALE 0.0395284707521047416f   // 640^-0.5

// ---------------- scratch (device globals) ----------------
__device__ __nv_bfloat16 g_xh[(size_t)M_TOT * DIM];
__device__ __nv_bfloat16 g_xl[(size_t)M_TOT * DIM];
__device__ __nv_bfloat16 g_wqh[(size_t)QKV_N * DIM];   // w_qkv^T hi  [1920][640]
__device__ __nv_bfloat16 g_wql[(size_t)QKV_N * DIM];
__device__ __nv_bfloat16 g_woh[(size_t)DIM * DIM];     // w_out^T hi  [640][640]
__device__ __nv_bfloat16 g_wol[(size_t)DIM * DIM];
// per-head q/k/v, bf16 hi/lo: [B*HEADS][SEQ][64]
__device__ __nv_bfloat16 g_qh[(size_t)B_SZ * HEADS * SEQ * HD];
__device__ __nv_bfloat16 g_ql[(size_t)B_SZ * HEADS * SEQ * HD];
__device__ __nv_bfloat16 g_kh[(size_t)B_SZ * HEADS * SEQ * HD];
__device__ __nv_bfloat16 g_kl[(size_t)B_SZ * HEADS * SEQ * HD];
__device__ __nv_bfloat16 g_vh[(size_t)B_SZ * HEADS * SEQ * HD];
__device__ __nv_bfloat16 g_vl[(size_t)B_SZ * HEADS * SEQ * HD];
__device__ __nv_bfloat16 g_ah[(size_t)M_TOT * DIM];    // attention out hi (bf16 split)
__device__ __nv_bfloat16 g_al[(size_t)M_TOT * DIM];

// ---------------- helpers ----------------
__device__ __forceinline__ uint32_t smem_u32(const void* p) {
    uint32_t a;
    asm("{ .reg .u64 t; cvta.to.shared.u64 t, %1; cvt.u32.u64 %0, t; }"
        : "=r"(a) : "l"(p));
    return a;
}
__device__ __forceinline__ void ldmatrix_x4(uint32_t* r, uint32_t addr) {
    asm volatile("ldmatrix.sync.aligned.m8n8.x4.shared.b16 {%0,%1,%2,%3}, [%4];"
                 : "=r"(r[0]), "=r"(r[1]), "=r"(r[2]), "=r"(r[3]) : "r"(addr));
}
__device__ __forceinline__ void ldmatrix_x2(uint32_t* r, uint32_t addr) {
    asm volatile("ldmatrix.sync.aligned.m8n8.x2.shared.b16 {%0,%1}, [%2];"
                 : "=r"(r[0]), "=r"(r[1]) : "r"(addr));
}
__device__ __forceinline__ void ldmatrix_x2_trans(uint32_t* r, uint32_t addr) {
    asm volatile("ldmatrix.sync.aligned.m8n8.x2.trans.shared.b16 {%0,%1}, [%2];"
                 : "=r"(r[0]), "=r"(r[1]) : "r"(addr));
}
__device__ __forceinline__ void mma_bf16(float* c, const uint32_t* a, const uint32_t* b) {
    asm volatile("mma.sync.aligned.m16n8k16.row.col.f32.bf16.bf16.f32 "
                 "{%0,%1,%2,%3}, {%4,%5,%6,%7}, {%8,%9}, {%0,%1,%2,%3};"
                 : "+f"(c[0]), "+f"(c[1]), "+f"(c[2]), "+f"(c[3])
                 : "r"(a[0]), "r"(a[1]), "r"(a[2]), "r"(a[3]), "r"(b[0]), "r"(b[1]));
}
// pack (x,y) into bf16x2 hi + lo-residual bf16x2
__device__ __forceinline__ void split2(float x, float y, uint32_t& hi, uint32_t& lo) {
    __nv_bfloat162 h;
    h.x = __float2bfloat16(x);
    h.y = __float2bfloat16(y);
    __nv_bfloat162 l;
    l.x = __float2bfloat16(x - __bfloat162float(h.x));
    l.y = __float2bfloat16(y - __bfloat162float(h.y));
    hi = *(uint32_t*)&h;
    lo = *(uint32_t*)&l;
}

// 64B-row tile (32 bf16), chunk^((row>>1)&3) swizzle — for GEMM BK=32 tiles
__device__ __forceinline__ uint32_t tile_off(int row, int chunk) {
    return (uint32_t)(row * 64 + 16 * (chunk ^ ((row >> 1) & 3)));
}
// 128B-row tile (64 bf16), chunk^(row&7) swizzle — for flash Q/K/V tiles
__device__ __forceinline__ uint32_t foff(int row, int chunk) {
    return (uint32_t)(row * 128 + 16 * (chunk ^ (row & 7)));
}

// ---------------- conversion kernels ----------------
__global__ void split_f32(const float* __restrict__ in,
                          __nv_bfloat16* __restrict__ hi,
                          __nv_bfloat16* __restrict__ lo, int n)
{
    int i = blockIdx.x * 256 + threadIdx.x;
    if (i < n) {
        float v = in[i];
        __nv_bfloat16 h = __float2bfloat16(v);
        hi[i] = h;
        lo[i] = __float2bfloat16(v - __bfloat162float(h));
    }
}
__global__ void splitT_f32(const float* __restrict__ w,
                           __nv_bfloat16* __restrict__ hiT,
                           __nv_bfloat16* __restrict__ loT, int K, int N)
{
    int i = blockIdx.x * 256 + threadIdx.x;
    if (i < K * N) {
        int k = i / N, n = i - k * N;
        float v = w[i];
        __nv_bfloat16 h = __float2bfloat16(v);
        hiT[(size_t)n * K + k] = h;
        loT[(size_t)n * K + k] = __float2bfloat16(v - __bfloat162float(h));
    }
}

// ---------------- mma.sync split-bf16 GEMM ----------------
// C[M,N] = A[M,K] @ B^T[N,K] + bias. CTA 128x128, BK=32, 8 warps, warp 64x32.
// QKV=true: write bf16 hi/lo per-head q/k/v instead of fp32 C.
template <bool QKV>
__global__ __launch_bounds__(256, 2)
void gemm_mma(const __nv_bfloat16* __restrict__ Ah, const __nv_bfloat16* __restrict__ Al,
              const __nv_bfloat16* __restrict__ Bh, const __nv_bfloat16* __restrict__ Bl,
              const float* __restrict__ bias, float* __restrict__ Cout,
              int Ntot, int Ktot)
{
    __shared__ __nv_bfloat16 sAh[128 * 32], sAl[128 * 32];
    __shared__ __nv_bfloat16 sBh[128 * 32], sBl[128 * 32];

    const int tid  = threadIdx.x;
    const int lane = tid & 31;
    const int wid  = tid >> 5;
    const int wm   = wid >> 2;
    const int wn   = wid & 3;
    const int m0   = blockIdx.y * 128;
    const int n0   = blockIdx.x * 128;

    const uint32_t aAh = smem_u32(sAh), aAl = smem_u32(sAl);
    const uint32_t aBh = smem_u32(sBh), aBl = smem_u32(sBl);

    float c[4][4][4];
    #pragma unroll
    for (int i = 0; i < 4; ++i)
        #pragma unroll
        for (int j = 0; j < 4; ++j)
            #pragma unroll
            for (int t = 0; t < 4; ++t) c[i][j][t] = 0.f;

    for (int k0 = 0; k0 < Ktot; k0 += 32) {
        #pragma unroll
        for (int it = 0; it < 2; ++it) {
            const int idx = it * 256 + tid;
            const int row = idx >> 2;
            const int cc  = idx & 3;
            const uint32_t so = tile_off(row, cc);
            const size_t ga = (size_t)(m0 + row) * Ktot + k0 + cc * 8;
            const size_t gb = (size_t)(n0 + row) * Ktot + k0 + cc * 8;
            *(uint4*)((char*)sAh + so) = *(const uint4*)(Ah + ga);
            *(uint4*)((char*)sAl + so) = *(const uint4*)(Al + ga);
            *(uint4*)((char*)sBh + so) = *(const uint4*)(Bh + gb);
            *(uint4*)((char*)sBl + so) = *(const uint4*)(Bl + gb);
        }
        __syncthreads();

        #pragma unroll
        for (int ks = 0; ks < 2; ++ks) {
            uint32_t bh[4][2], bl[4][2];
            const int lr = lane & 7;
            const int lc = (lane >> 3) & 1;
            #pragma unroll
            for (int ni = 0; ni < 4; ++ni) {
                const int r = wn * 32 + ni * 8 + lr;
                const uint32_t off = tile_off(r, ks * 2 + lc);
                ldmatrix_x2(bh[ni], aBh + off);
                ldmatrix_x2(bl[ni], aBl + off);
            }
            #pragma unroll
            for (int mi = 0; mi < 4; ++mi) {
                uint32_t ah[4], al[4];
                const int r = wm * 64 + mi * 16 + (lane & 15);
                const uint32_t off = tile_off(r, ks * 2 + (lane >> 4));
                ldmatrix_x4(ah, aAh + off);
                ldmatrix_x4(al, aAl + off);
                #pragma unroll
                for (int ni = 0; ni < 4; ++ni) {
                    mma_bf16(c[mi][ni], ah, bh[ni]);
                    mma_bf16(c[mi][ni], ah, bl[ni]);
                    mma_bf16(c[mi][ni], al, bh[ni]);
                }
            }
        }
        __syncthreads();
    }

    #pragma unroll
    for (int mi = 0; mi < 4; ++mi) {
        #pragma unroll
        for (int ni = 0; ni < 4; ++ni) {
            const int r0  = m0 + wm * 64 + mi * 16 + (lane >> 2);
            const int col = n0 + wn * 32 + ni * 8 + (lane & 3) * 2;
            const float b0 = bias[col], b1 = bias[col + 1];
            #pragma unroll
            for (int half = 0; half < 2; ++half) {
                const int r = r0 + half * 8;
                const float vx = c[mi][ni][half * 2 + 0] + b0;
                const float vy = c[mi][ni][half * 2 + 1] + b1;
                if (QKV) {
                    const int bb  = r >> 10;
                    const int iq  = r & 1023;
                    const int sel = col / DIM;
                    const int nc  = col - sel * DIM;
                    const int h   = nc >> 6;
                    const int d   = nc & 63;
                    __nv_bfloat16* dh = (sel == 0) ? g_qh : (sel == 1) ? g_kh : g_vh;
                    __nv_bfloat16* dl = (sel == 0) ? g_ql : (sel == 1) ? g_kl : g_vl;
                    const size_t idx = (((size_t)(bb * HEADS + h)) * SEQ + iq) * HD + d;
                    uint32_t hi, lo;
                    split2(vx, vy, hi, lo);
                    *(uint32_t*)(dh + idx) = hi;
                    *(uint32_t*)(dl + idx) = lo;
                } else {
                    float2 v; v.x = vx; v.y = vy;
                    *(float2*)&Cout[(size_t)r * Ntot + col] = v;
                }
            }
        }
    }
}

// ---------------- flash attention with mma.sync ----------------
// grid (SEQ/128, B*HEADS), 256 thr (8 warps x 16 q-rows). 64-key blocks.
// smem: [Qh 16K][Ql 16K][Kh 8K][Kl 8K][Vh 8K][Vl 8K] = 64KB dynamic.
#define FQH 0
#define FQL 16384
#define FKH 32768
#define FKL 40960
#define FVH 49152
#define FVL 57344
#define FLASH_SMEM 65536

__global__ __launch_bounds__(256)
void flash_mma()
{
    extern __shared__ char fs[];
    const uint32_t sb = smem_u32(fs);
    const int tid  = threadIdx.x;
    const int lane = tid & 31;
    const int wid  = tid >> 5;
    const int bh   = blockIdx.y;
    const int q0   = blockIdx.x * 128;
    const size_t base = (size_t)bh * SEQ * HD;

    // stage Q block (128x64 hi/lo)
    #pragma unroll
    for (int i = 0; i < 4; ++i) {
        const int idx = i * 256 + tid;         // 0..1023
        const int row = idx >> 3, ch = idx & 7;
        const uint32_t so = foff(row, ch);
        const size_t g = base + (size_t)(q0 + row) * HD + ch * 8;
        *(uint4*)(fs + FQH + so) = *(const uint4*)(g_qh + g);
        *(uint4*)(fs + FQL + so) = *(const uint4*)(g_ql + g);
    }
    __syncthreads();

    float O[8][4];
    #pragma unroll
    for (int i = 0; i < 8; ++i)
        #pragma unroll
        for (int t = 0; t < 4; ++t) O[i][t] = 0.f;
    float m0 = -1e30f, m1 = -1e30f, l0 = 0.f, l1 = 0.f;

    for (int kb = 0; kb < SEQ; kb += 64) {
        __syncthreads();
        #pragma unroll
        for (int i = 0; i < 2; ++i) {
            const int idx = i * 256 + tid;     // 0..511
            const int row = idx >> 3, ch = idx & 7;
            const uint32_t so = foff(row, ch);
            const size_t g = base + (size_t)(kb + row) * HD + ch * 8;
            *(uint4*)(fs + FKH + so) = *(const uint4*)(g_kh + g);
            *(uint4*)(fs + FKL + so) = *(const uint4*)(g_kl + g);
            *(uint4*)(fs + FVH + so) = *(const uint4*)(g_vh + g);
            *(uint4*)(fs + FVL + so) = *(const uint4*)(g_vl + g);
        }
        __syncthreads();

        // S = Q K^T  (128x64 per CTA; 16x64 per warp)
        float c[8][4];
        #pragma unroll
        for (int i = 0; i < 8; ++i)
            #pragma unroll
            for (int t = 0; t < 4; ++t) c[i][t] = 0.f;

        #pragma unroll
        for (int ks = 0; ks < 4; ++ks) {
            uint32_t qh[4], ql[4];
            {
                const int r  = wid * 16 + (lane & 15);
                const int ch = ks * 2 + (lane >> 4);
                ldmatrix_x4(qh, sb + FQH + foff(r, ch));
                ldmatrix_x4(ql, sb + FQL + foff(r, ch));
            }
            const int lr = lane & 7;
            const int lc = (lane >> 3) & 1;
            #pragma unroll
            for (int ni = 0; ni < 8; ++ni) {
                uint32_t bh2[2], bl2[2];
                const uint32_t off = foff(ni * 8 + lr, ks * 2 + lc);
                ldmatrix_x2(bh2, sb + FKH + off);
                ldmatrix_x2(bl2, sb + FKL + off);
                mma_bf16(c[ni], qh, bh2);
                mma_bf16(c[ni], qh, bl2);
                mma_bf16(c[ni], ql, bh2);
            }
        }

        // scale + online softmax (rows: r0=lane>>2, r1=r0+8)
        float rm0 = -1e30f, rm1 = -1e30f;
        #pragma unroll
        for (int ni = 0; ni < 8; ++ni) {
            #pragma unroll
            for (int t = 0; t < 4; ++t) c[ni][t] *= ATT_SCALE;
            rm0 = fmaxf(rm0, fmaxf(c[ni][0], c[ni][1]));
            rm1 = fmaxf(rm1, fmaxf(c[ni][2], c[ni][3]));
        }
        #pragma unroll
        for (int off = 1; off < 4; off <<= 1) {
            rm0 = fmaxf(rm0, __shfl_xor_sync(0xffffffffu, rm0, off));
            rm1 = fmaxf(rm1, __shfl_xor_sync(0xffffffffu, rm1, off));
        }
        const float mn0 = fmaxf(m0, rm0), mn1 = fmaxf(m1, rm1);
        const float cor0 = __expf(m0 - mn0), cor1 = __expf(m1 - mn1);
        m0 = mn0; m1 = mn1;

        float rs0 = 0.f, rs1 = 0.f;
        #pragma unroll
        for (int ni = 0; ni < 8; ++ni) {
            c[ni][0] = __expf(c[ni][0] - m0);
            c[ni][1] = __expf(c[ni][1] - m0);
            c[ni][2] = __expf(c[ni][2] - m1);
            c[ni][3] = __expf(c[ni][3] - m1);
            rs0 += c[ni][0] + c[ni][1];
            rs1 += c[ni][2] + c[ni][3];
        }
        #pragma unroll
        for (int off = 1; off < 4; off <<= 1) {
            rs0 += __shfl_xor_sync(0xffffffffu, rs0, off);
            rs1 += __shfl_xor_sync(0xffffffffu, rs1, off);
        }
        l0 = l0 * cor0 + rs0;
        l1 = l1 * cor1 + rs1;
        #pragma unroll
        for (int nd = 0; nd < 8; ++nd) {
            O[nd][0] *= cor0; O[nd][1] *= cor0;
            O[nd][2] *= cor1; O[nd][3] *= cor1;
        }

        // O += P V   (P from c-frags; A-frag = repacked C-frag)
        #pragma unroll
        for (int ks2 = 0; ks2 < 4; ++ks2) {
            uint32_t ph[4], pl[4];
            split2(c[2*ks2][0],   c[2*ks2][1],   ph[0], pl[0]);
            split2(c[2*ks2][2],   c[2*ks2][3],   ph[1], pl[1]);
            split2(c[2*ks2+1][0], c[2*ks2+1][1], ph[2], pl[2]);
            split2(c[2*ks2+1][2], c[2*ks2+1][3], ph[3], pl[3]);
            const int vr = ks2 * 16 + (lane & 15);
            #pragma unroll
            for (int nd = 0; nd < 8; ++nd) {
                uint32_t vh2[2], vl2[2];
                const uint32_t off = foff(vr, nd);
                ldmatrix_x2_trans(vh2, sb + FVH + off);
                ldmatrix_x2_trans(vl2, sb + FVL + off);
                mma_bf16(O[nd], ph, vh2);
                mma_bf16(O[nd], ph, vl2);
                mma_bf16(O[nd], pl, vh2);
            }
        }
    }

    // epilogue: O/l -> g_ah/g_al  [B,N,DIM] bf16 hi/lo
    const float inv0 = 1.f / l0, inv1 = 1.f / l1;
    const int b = bh / HEADS;
    const int h = bh - b * HEADS;
    const int r0 = q0 + wid * 16 + (lane >> 2);
    #pragma unroll
    for (int nd = 0; nd < 8; ++nd) {
        const int col = h * HD + nd * 8 + (lane & 3) * 2;
        uint32_t hi, lo;
        split2(O[nd][0] * inv0, O[nd][1] * inv0, hi, lo);
        size_t idx = ((size_t)(b * SEQ + r0)) * DIM + col;
        *(uint32_t*)(g_ah + idx) = hi;
        *(uint32_t*)(g_al + idx) = lo;
        split2(O[nd][2] * inv1, O[nd][3] * inv1, hi, lo);
        idx = ((size_t)(b * SEQ + r0 + 8)) * DIM + col;
        *(uint32_t*)(g_ah + idx) = hi;
        *(uint32_t*)(g_al + idx) = lo;
    }
}

// ---------------- launch ----------------
extern "C" void kernel_launch(void* const* d_in, const int* in_sizes, int n_in,
                              void* d_out, int out_size)
{
    const float* x     = (const float*)d_in[0];
    const float* w_qkv = (const float*)d_in[1];
    const float* b_qkv = (const float*)d_in[2];
    const float* w_out = (const float*)d_in[3];
    const float* b_out = (const float*)d_in[4];
    float* out = (float*)d_out;

    __nv_bfloat16 *xh, *xl, *wqh, *wql, *woh, *wol, *ah, *al;
    cudaGetSymbolAddress((void**)&xh,  g_xh);
    cudaGetSymbolAddress((void**)&xl,  g_xl);
    cudaGetSymbolAddress((void**)&wqh, g_wqh);
    cudaGetSymbolAddress((void**)&wql, g_wql);
    cudaGetSymbolAddress((void**)&woh, g_woh);
    cudaGetSymbolAddress((void**)&wol, g_wol);
    cudaGetSymbolAddress((void**)&ah,  g_ah);
    cudaGetSymbolAddress((void**)&al,  g_al);

    cudaFuncSetAttribute(flash_mma, cudaFuncAttributeMaxDynamicSharedMemorySize, FLASH_SMEM);

    // 0) fp32 -> bf16 hi/lo splits
    const int nx = M_TOT * DIM;
    split_f32<<<(nx + 255) / 256, 256>>>(x, xh, xl, nx);
    splitT_f32<<<(DIM * QKV_N + 255) / 256, 256>>>(w_qkv, wqh, wql, DIM, QKV_N);
    splitT_f32<<<(DIM * DIM + 255) / 256, 256>>>(w_out, woh, wol, DIM, DIM);

    // 1) QKV GEMM -> per-head bf16 hi/lo q/k/v
    gemm_mma<true><<<dim3(QKV_N / 128, M_TOT / 128), 256>>>(
        xh, xl, wqh, wql, b_qkv, nullptr, QKV_N, DIM);

    // 2) flash attention (HMMA) -> g_ah/g_al
    flash_mma<<<dim3(SEQ / 128, B_SZ * HEADS), 256, FLASH_SMEM>>>();

    // 3) out projection (HMMA) -> d_out
    gemm_mma<false><<<dim3(DIM / 128, M_TOT / 128), 256>>>(
        ah, al, woh, wol, b_out, out, DIM, DIM);
}

// round 5
// speedup vs baseline: 3.5690x; 1.1825x over previous
#include <cuda_runtime.h>
#include <cuda_bf16.h>
#include <cstdint>

#define DIM     640
#define HEADS   10
#define HD      64
#define B_SZ    16
#define SEQ     1024
#define M_TOT   (B_SZ * SEQ)     // 16384
#define QKV_N   (3 * DIM)        // 1920
#define ATT_SCALE 0.0395284707521047416f   // 640^-0.5

// ---------------- scratch (device globals) ----------------
__device__ __nv_bfloat16 g_xh[(size_t)M_TOT * DIM];
__device__ __nv_bfloat16 g_xl[(size_t)M_TOT * DIM];
__device__ __nv_bfloat16 g_wqh[(size_t)QKV_N * DIM];   // w_qkv^T hi  [1920][640]
__device__ __nv_bfloat16 g_wql[(size_t)QKV_N * DIM];
__device__ __nv_bfloat16 g_woh[(size_t)DIM * DIM];     // w_out^T hi  [640][640]
__device__ __nv_bfloat16 g_wol[(size_t)DIM * DIM];
// per-head q/k/v, bf16 hi/lo: [B*HEADS][SEQ][64]
__device__ __nv_bfloat16 g_qh[(size_t)B_SZ * HEADS * SEQ * HD];
__device__ __nv_bfloat16 g_ql[(size_t)B_SZ * HEADS * SEQ * HD];
__device__ __nv_bfloat16 g_kh[(size_t)B_SZ * HEADS * SEQ * HD];
__device__ __nv_bfloat16 g_kl[(size_t)B_SZ * HEADS * SEQ * HD];
__device__ __nv_bfloat16 g_vh[(size_t)B_SZ * HEADS * SEQ * HD];
__device__ __nv_bfloat16 g_vl[(size_t)B_SZ * HEADS * SEQ * HD];
__device__ __nv_bfloat16 g_ah[(size_t)M_TOT * DIM];    // attention out hi (bf16 split)
__device__ __nv_bfloat16 g_al[(size_t)M_TOT * DIM];

// ---------------- helpers ----------------
__device__ __forceinline__ uint32_t smem_u32(const void* p) {
    uint32_t a;
    asm("{ .reg .u64 t; cvta.to.shared.u64 t, %1; cvt.u32.u64 %0, t; }"
        : "=r"(a) : "l"(p));
    return a;
}
__device__ __forceinline__ void ldmatrix_x4(uint32_t* r, uint32_t addr) {
    asm volatile("ldmatrix.sync.aligned.m8n8.x4.shared.b16 {%0,%1,%2,%3}, [%4];"
                 : "=r"(r[0]), "=r"(r[1]), "=r"(r[2]), "=r"(r[3]) : "r"(addr));
}
__device__ __forceinline__ void ldmatrix_x2(uint32_t* r, uint32_t addr) {
    asm volatile("ldmatrix.sync.aligned.m8n8.x2.shared.b16 {%0,%1}, [%2];"
                 : "=r"(r[0]), "=r"(r[1]) : "r"(addr));
}
__device__ __forceinline__ void ldmatrix_x2_trans(uint32_t* r, uint32_t addr) {
    asm volatile("ldmatrix.sync.aligned.m8n8.x2.trans.shared.b16 {%0,%1}, [%2];"
                 : "=r"(r[0]), "=r"(r[1]) : "r"(addr));
}
__device__ __forceinline__ void mma_bf16(float* c, const uint32_t* a, const uint32_t* b) {
    asm volatile("mma.sync.aligned.m16n8k16.row.col.f32.bf16.bf16.f32 "
                 "{%0,%1,%2,%3}, {%4,%5,%6,%7}, {%8,%9}, {%0,%1,%2,%3};"
                 : "+f"(c[0]), "+f"(c[1]), "+f"(c[2]), "+f"(c[3])
                 : "r"(a[0]), "r"(a[1]), "r"(a[2]), "r"(a[3]), "r"(b[0]), "r"(b[1]));
}
__device__ __forceinline__ void split2(float x, float y, uint32_t& hi, uint32_t& lo) {
    __nv_bfloat162 h;
    h.x = __float2bfloat16(x);
    h.y = __float2bfloat16(y);
    __nv_bfloat162 l;
    l.x = __float2bfloat16(x - __bfloat162float(h.x));
    l.y = __float2bfloat16(y - __bfloat162float(h.y));
    hi = *(uint32_t*)&h;
    lo = *(uint32_t*)&l;
}

#define CPASYNC(dst, src) \
    asm volatile("cp.async.cg.shared.global [%0], [%1], 16;" \
                 :: "r"(dst), "l"(src) : "memory")
#define CPCOMMIT() asm volatile("cp.async.commit_group;" ::: "memory")
#define CPWAIT1()  asm volatile("cp.async.wait_group 1;" ::: "memory")
#define CPWAIT0()  asm volatile("cp.async.wait_group 0;" ::: "memory")

// 64B-row tile (32 bf16), chunk^((row>>1)&3) swizzle — GEMM BK=32 tiles
__device__ __forceinline__ uint32_t tile_off(int row, int chunk) {
    return (uint32_t)(row * 64 + 16 * (chunk ^ ((row >> 1) & 3)));
}
// 128B-row tile (64 bf16), chunk^(row&7) swizzle — flash Q/K/V tiles
__device__ __forceinline__ uint32_t foff(int row, int chunk) {
    return (uint32_t)(row * 128 + 16 * (chunk ^ (row & 7)));
}

// ---------------- conversion kernels ----------------
__global__ void split_f32(const float* __restrict__ in,
                          __nv_bfloat16* __restrict__ hi,
                          __nv_bfloat16* __restrict__ lo, int n)
{
    int i = blockIdx.x * 256 + threadIdx.x;
    if (i < n) {
        float v = in[i];
        __nv_bfloat16 h = __float2bfloat16(v);
        hi[i] = h;
        lo[i] = __float2bfloat16(v - __bfloat162float(h));
    }
}
__global__ void splitT_f32(const float* __restrict__ w,
                           __nv_bfloat16* __restrict__ hiT,
                           __nv_bfloat16* __restrict__ loT, int K, int N)
{
    int i = blockIdx.x * 256 + threadIdx.x;
    if (i < K * N) {
        int k = i / N, n = i - k * N;
        float v = w[i];
        __nv_bfloat16 h = __float2bfloat16(v);
        hiT[(size_t)n * K + k] = h;
        loT[(size_t)n * K + k] = __float2bfloat16(v - __bfloat162float(h));
    }
}

// ---------------- mma.sync split-bf16 GEMM (cp.async 2-stage) ----------------
// C[M,N] = A[M,K] @ B^T[N,K] + bias. CTA 128x128, BK=32, 8 warps, warp 64x32.
// smem stage: [Ah 8K][Al 8K][Bh 8K][Bl 8K] = 32KB; 2 stages = 64KB dynamic.
#define GS_STAGE 32768
#define GS_AL    8192
#define GS_BH    16384
#define GS_BL    24576
#define GEMM_SMEM (2 * GS_STAGE)

template <bool QKV>
__global__ __launch_bounds__(256, 2)
void gemm_mma(const __nv_bfloat16* __restrict__ Ah, const __nv_bfloat16* __restrict__ Al,
              const __nv_bfloat16* __restrict__ Bh, const __nv_bfloat16* __restrict__ Bl,
              const float* __restrict__ bias, float* __restrict__ Cout,
              int Ntot, int Ktot)
{
    extern __shared__ char gs[];
    const uint32_t sb = smem_u32(gs);

    const int tid  = threadIdx.x;
    const int lane = tid & 31;
    const int wid  = tid >> 5;
    const int wm   = wid >> 2;
    const int wn   = wid & 3;
    const int m0   = blockIdx.y * 128;
    const int n0   = blockIdx.x * 128;

    float c[4][4][4];
    #pragma unroll
    for (int i = 0; i < 4; ++i)
        #pragma unroll
        for (int j = 0; j < 4; ++j)
            #pragma unroll
            for (int t = 0; t < 4; ++t) c[i][j][t] = 0.f;

    auto load_stage = [&](int stage, int k0) {
        const uint32_t s0 = sb + stage * GS_STAGE;
        #pragma unroll
        for (int it = 0; it < 2; ++it) {
            const int idx = it * 256 + tid;
            const int row = idx >> 2;
            const int cc  = idx & 3;
            const uint32_t so = tile_off(row, cc);
            const size_t ga = (size_t)(m0 + row) * Ktot + k0 + cc * 8;
            const size_t gb = (size_t)(n0 + row) * Ktot + k0 + cc * 8;
            CPASYNC(s0 + so,         Ah + ga);
            CPASYNC(s0 + GS_AL + so, Al + ga);
            CPASYNC(s0 + GS_BH + so, Bh + gb);
            CPASYNC(s0 + GS_BL + so, Bl + gb);
        }
        CPCOMMIT();
    };

    const int nk = Ktot / 32;
    load_stage(0, 0);

    for (int ki = 0; ki < nk; ++ki) {
        if (ki + 1 < nk) {
            load_stage((ki + 1) & 1, (ki + 1) * 32);
            CPWAIT1();
        } else {
            CPWAIT0();
        }
        __syncthreads();

        const uint32_t s0 = sb + (ki & 1) * GS_STAGE;
        #pragma unroll
        for (int ks = 0; ks < 2; ++ks) {
            uint32_t bh[4][2], bl[4][2];
            const int lr = lane & 7;
            const int lc = (lane >> 3) & 1;
            #pragma unroll
            for (int ni = 0; ni < 4; ++ni) {
                const int r = wn * 32 + ni * 8 + lr;
                const uint32_t off = tile_off(r, ks * 2 + lc);
                ldmatrix_x2(bh[ni], s0 + GS_BH + off);
                ldmatrix_x2(bl[ni], s0 + GS_BL + off);
            }
            #pragma unroll
            for (int mi = 0; mi < 4; ++mi) {
                uint32_t ah[4], al[4];
                const int r = wm * 64 + mi * 16 + (lane & 15);
                const uint32_t off = tile_off(r, ks * 2 + (lane >> 4));
                ldmatrix_x4(ah, s0 + off);
                ldmatrix_x4(al, s0 + GS_AL + off);
                #pragma unroll
                for (int ni = 0; ni < 4; ++ni) {
                    mma_bf16(c[mi][ni], ah, bh[ni]);
                    mma_bf16(c[mi][ni], ah, bl[ni]);
                    mma_bf16(c[mi][ni], al, bh[ni]);
                }
            }
        }
        __syncthreads();
    }

    #pragma unroll
    for (int mi = 0; mi < 4; ++mi) {
        #pragma unroll
        for (int ni = 0; ni < 4; ++ni) {
            const int r0  = m0 + wm * 64 + mi * 16 + (lane >> 2);
            const int col = n0 + wn * 32 + ni * 8 + (lane & 3) * 2;
            const float b0 = bias[col], b1 = bias[col + 1];
            #pragma unroll
            for (int half = 0; half < 2; ++half) {
                const int r = r0 + half * 8;
                const float vx = c[mi][ni][half * 2 + 0] + b0;
                const float vy = c[mi][ni][half * 2 + 1] + b1;
                if (QKV) {
                    const int bb  = r >> 10;
                    const int iq  = r & 1023;
                    const int sel = col / DIM;
                    const int nc  = col - sel * DIM;
                    const int h   = nc >> 6;
                    const int d   = nc & 63;
                    __nv_bfloat16* dh = (sel == 0) ? g_qh : (sel == 1) ? g_kh : g_vh;
                    __nv_bfloat16* dl = (sel == 0) ? g_ql : (sel == 1) ? g_kl : g_vl;
                    const size_t idx = (((size_t)(bb * HEADS + h)) * SEQ + iq) * HD + d;
                    uint32_t hi, lo;
                    split2(vx, vy, hi, lo);
                    *(uint32_t*)(dh + idx) = hi;
                    *(uint32_t*)(dl + idx) = lo;
                } else {
                    float2 v; v.x = vx; v.y = vy;
                    *(float2*)&Cout[(size_t)r * Ntot + col] = v;
                }
            }
        }
    }
}

// ---------------- flash attention with mma.sync (cp.async 2-stage K/V) ----------------
// grid (SEQ/128, B*HEADS), 256 thr. Q resident 32KB; K/V stages 2x32KB = 96KB.
#define FQH 0
#define FQL 16384
#define FKV 32768
#define FKV_STRIDE 32768
#define FKL_O 8192
#define FVH_O 16384
#define FVL_O 24576
#define FLASH_SMEM (32768 + 2 * FKV_STRIDE)   // 98304

__global__ __launch_bounds__(256)
void flash_mma()
{
    extern __shared__ char fs[];
    const uint32_t sb = smem_u32(fs);
    const int tid  = threadIdx.x;
    const int lane = tid & 31;
    const int wid  = tid >> 5;
    const int bh   = blockIdx.y;
    const int q0   = blockIdx.x * 128;
    const size_t base = (size_t)bh * SEQ * HD;

    auto load_kv = [&](int stage, int kb) {
        const uint32_t s0 = sb + FKV + stage * FKV_STRIDE;
        #pragma unroll
        for (int i = 0; i < 2; ++i) {
            const int idx = i * 256 + tid;     // 0..511
            const int row = idx >> 3, ch = idx & 7;
            const uint32_t so = foff(row, ch);
            const size_t g = base + (size_t)(kb + row) * HD + ch * 8;
            CPASYNC(s0 + so,         g_kh + g);
            CPASYNC(s0 + FKL_O + so, g_kl + g);
            CPASYNC(s0 + FVH_O + so, g_vh + g);
            CPASYNC(s0 + FVL_O + so, g_vl + g);
        }
        CPCOMMIT();
    };

    // start first K/V load, then stage Q while it flies
    load_kv(0, 0);
    #pragma unroll
    for (int i = 0; i < 4; ++i) {
        const int idx = i * 256 + tid;         // 0..1023
        const int row = idx >> 3, ch = idx & 7;
        const uint32_t so = foff(row, ch);
        const size_t g = base + (size_t)(q0 + row) * HD + ch * 8;
        *(uint4*)(fs + FQH + so) = *(const uint4*)(g_qh + g);
        *(uint4*)(fs + FQL + so) = *(const uint4*)(g_ql + g);
    }

    float O[8][4];
    #pragma unroll
    for (int i = 0; i < 8; ++i)
        #pragma unroll
        for (int t = 0; t < 4; ++t) O[i][t] = 0.f;
    float m0 = -1e30f, m1 = -1e30f, l0 = 0.f, l1 = 0.f;

    const int nkb = SEQ / 64;
    for (int kbi = 0; kbi < nkb; ++kbi) {
        if (kbi + 1 < nkb) {
            load_kv((kbi + 1) & 1, (kbi + 1) * 64);
            CPWAIT1();
        } else {
            CPWAIT0();
        }
        __syncthreads();
        const uint32_t s0 = sb + FKV + (kbi & 1) * FKV_STRIDE;

        // S = Q K^T  (128x64 per CTA; 16x64 per warp)
        float c[8][4];
        #pragma unroll
        for (int i = 0; i < 8; ++i)
            #pragma unroll
            for (int t = 0; t < 4; ++t) c[i][t] = 0.f;

        #pragma unroll
        for (int ks = 0; ks < 4; ++ks) {
            uint32_t qh[4], ql[4];
            {
                const int r  = wid * 16 + (lane & 15);
                const int ch = ks * 2 + (lane >> 4);
                ldmatrix_x4(qh, sb + FQH + foff(r, ch));
                ldmatrix_x4(ql, sb + FQL + foff(r, ch));
            }
            const int lr = lane & 7;
            const int lc = (lane >> 3) & 1;
            #pragma unroll
            for (int ni = 0; ni < 8; ++ni) {
                uint32_t bh2[2], bl2[2];
                const uint32_t off = foff(ni * 8 + lr, ks * 2 + lc);
                ldmatrix_x2(bh2, s0 + off);
                ldmatrix_x2(bl2, s0 + FKL_O + off);
                mma_bf16(c[ni], qh, bh2);
                mma_bf16(c[ni], qh, bl2);
                mma_bf16(c[ni], ql, bh2);
            }
        }

        // scale + online softmax
        float rm0 = -1e30f, rm1 = -1e30f;
        #pragma unroll
        for (int ni = 0; ni < 8; ++ni) {
            #pragma unroll
            for (int t = 0; t < 4; ++t) c[ni][t] *= ATT_SCALE;
            rm0 = fmaxf(rm0, fmaxf(c[ni][0], c[ni][1]));
            rm1 = fmaxf(rm1, fmaxf(c[ni][2], c[ni][3]));
        }
        #pragma unroll
        for (int off = 1; off < 4; off <<= 1) {
            rm0 = fmaxf(rm0, __shfl_xor_sync(0xffffffffu, rm0, off));
            rm1 = fmaxf(rm1, __shfl_xor_sync(0xffffffffu, rm1, off));
        }
        const float mn0 = fmaxf(m0, rm0), mn1 = fmaxf(m1, rm1);
        const float cor0 = __expf(m0 - mn0), cor1 = __expf(m1 - mn1);
        m0 = mn0; m1 = mn1;

        float rs0 = 0.f, rs1 = 0.f;
        #pragma unroll
        for (int ni = 0; ni < 8; ++ni) {
            c[ni][0] = __expf(c[ni][0] - m0);
            c[ni][1] = __expf(c[ni][1] - m0);
            c[ni][2] = __expf(c[ni][2] - m1);
            c[ni][3] = __expf(c[ni][3] - m1);
            rs0 += c[ni][0] + c[ni][1];
            rs1 += c[ni][2] + c[ni][3];
        }
        #pragma unroll
        for (int off = 1; off < 4; off <<= 1) {
            rs0 += __shfl_xor_sync(0xffffffffu, rs0, off);
            rs1 += __shfl_xor_sync(0xffffffffu, rs1, off);
        }
        l0 = l0 * cor0 + rs0;
        l1 = l1 * cor1 + rs1;
        #pragma unroll
        for (int nd = 0; nd < 8; ++nd) {
            O[nd][0] *= cor0; O[nd][1] *= cor0;
            O[nd][2] *= cor1; O[nd][3] *= cor1;
        }

        // O += P V
        #pragma unroll
        for (int ks2 = 0; ks2 < 4; ++ks2) {
            uint32_t ph[4], pl[4];
            split2(c[2*ks2][0],   c[2*ks2][1],   ph[0], pl[0]);
            split2(c[2*ks2][2],   c[2*ks2][3],   ph[1], pl[1]);
            split2(c[2*ks2+1][0], c[2*ks2+1][1], ph[2], pl[2]);
            split2(c[2*ks2+1][2], c[2*ks2+1][3], ph[3], pl[3]);
            const int vr = ks2 * 16 + (lane & 15);
            #pragma unroll
            for (int nd = 0; nd < 8; ++nd) {
                uint32_t vh2[2], vl2[2];
                const uint32_t off = foff(vr, nd);
                ldmatrix_x2_trans(vh2, s0 + FVH_O + off);
                ldmatrix_x2_trans(vl2, s0 + FVL_O + off);
                mma_bf16(O[nd], ph, vh2);
                mma_bf16(O[nd], ph, vl2);
                mma_bf16(O[nd], pl, vh2);
            }
        }
        __syncthreads();
    }

    // epilogue
    const float inv0 = 1.f / l0, inv1 = 1.f / l1;
    const int b = bh / HEADS;
    const int h = bh - b * HEADS;
    const int r0 = q0 + wid * 16 + (lane >> 2);
    #pragma unroll
    for (int nd = 0; nd < 8; ++nd) {
        const int col = h * HD + nd * 8 + (lane & 3) * 2;
        uint32_t hi, lo;
        split2(O[nd][0] * inv0, O[nd][1] * inv0, hi, lo);
        size_t idx = ((size_t)(b * SEQ + r0)) * DIM + col;
        *(uint32_t*)(g_ah + idx) = hi;
        *(uint32_t*)(g_al + idx) = lo;
        split2(O[nd][2] * inv1, O[nd][3] * inv1, hi, lo);
        idx = ((size_t)(b * SEQ + r0 + 8)) * DIM + col;
        *(uint32_t*)(g_ah + idx) = hi;
        *(uint32_t*)(g_al + idx) = lo;
    }
}

// ---------------- launch ----------------
extern "C" void kernel_launch(void* const* d_in, const int* in_sizes, int n_in,
                              void* d_out, int out_size)
{
    const float* x     = (const float*)d_in[0];
    const float* w_qkv = (const float*)d_in[1];
    const float* b_qkv = (const float*)d_in[2];
    const float* w_out = (const float*)d_in[3];
    const float* b_out = (const float*)d_in[4];
    float* out = (float*)d_out;

    __nv_bfloat16 *xh, *xl, *wqh, *wql, *woh, *wol, *ah, *al;
    cudaGetSymbolAddress((void**)&xh,  g_xh);
    cudaGetSymbolAddress((void**)&xl,  g_xl);
    cudaGetSymbolAddress((void**)&wqh, g_wqh);
    cudaGetSymbolAddress((void**)&wql, g_wql);
    cudaGetSymbolAddress((void**)&woh, g_woh);
    cudaGetSymbolAddress((void**)&wol, g_wol);
    cudaGetSymbolAddress((void**)&ah,  g_ah);
    cudaGetSymbolAddress((void**)&al,  g_al);

    cudaFuncSetAttribute(gemm_mma<true>,  cudaFuncAttributeMaxDynamicSharedMemorySize, GEMM_SMEM);
    cudaFuncSetAttribute(gemm_mma<false>, cudaFuncAttributeMaxDynamicSharedMemorySize, GEMM_SMEM);
    cudaFuncSetAttribute(flash_mma, cudaFuncAttributeMaxDynamicSharedMemorySize, FLASH_SMEM);

    // 0) fp32 -> bf16 hi/lo splits
    const int nx = M_TOT * DIM;
    split_f32<<<(nx + 255) / 256, 256>>>(x, xh, xl, nx);
    splitT_f32<<<(DIM * QKV_N + 255) / 256, 256>>>(w_qkv, wqh, wql, DIM, QKV_N);
    splitT_f32<<<(DIM * DIM + 255) / 256, 256>>>(w_out, woh, wol, DIM, DIM);

    // 1) QKV GEMM -> per-head bf16 hi/lo q/k/v
    gemm_mma<true><<<dim3(QKV_N / 128, M_TOT / 128), 256, GEMM_SMEM>>>(
        xh, xl, wqh, wql, b_qkv, nullptr, QKV_N, DIM);

    // 2) flash attention (HMMA) -> g_ah/g_al
    flash_mma<<<dim3(SEQ / 128, B_SZ * HEADS), 256, FLASH_SMEM>>>();

    // 3) out projection (HMMA) -> d_out
    gemm_mma<false><<<dim3(DIM / 128, M_TOT / 128), 256, GEMM_SMEM>>>(
        ah, al, woh, wol, b_out, out, DIM, DIM);
}

// round 6
// speedup vs baseline: 3.9015x; 1.0932x over previous
#include <cuda_runtime.h>
#include <cuda_bf16.h>
#include <cstdint>

#define DIM     640
#define HEADS   10
#define HD      64
#define B_SZ    16
#define SEQ     1024
#define M_TOT   (B_SZ * SEQ)     // 16384
#define QKV_N   (3 * DIM)        // 1920
#define ATT_SCALE 0.0395284707521047416f   // 640^-0.5

// ---------------- scratch (device globals) ----------------
__device__ __nv_bfloat16 g_xh[(size_t)M_TOT * DIM];
__device__ __nv_bfloat16 g_xl[(size_t)M_TOT * DIM];
__device__ __nv_bfloat16 g_wqh[(size_t)QKV_N * DIM];   // w_qkv^T hi  [1920][640]
__device__ __nv_bfloat16 g_wql[(size_t)QKV_N * DIM];
__device__ __nv_bfloat16 g_woh[(size_t)DIM * DIM];     // w_out^T hi  [640][640]
__device__ __nv_bfloat16 g_wol[(size_t)DIM * DIM];
// per-head q/k/v, bf16 hi/lo: [B*HEADS][SEQ][64]
__device__ __nv_bfloat16 g_qh[(size_t)B_SZ * HEADS * SEQ * HD];
__device__ __nv_bfloat16 g_ql[(size_t)B_SZ * HEADS * SEQ * HD];
__device__ __nv_bfloat16 g_kh[(size_t)B_SZ * HEADS * SEQ * HD];
__device__ __nv_bfloat16 g_kl[(size_t)B_SZ * HEADS * SEQ * HD];
__device__ __nv_bfloat16 g_vh[(size_t)B_SZ * HEADS * SEQ * HD];
__device__ __nv_bfloat16 g_vl[(size_t)B_SZ * HEADS * SEQ * HD];
__device__ __nv_bfloat16 g_ah[(size_t)M_TOT * DIM];    // attention out hi (bf16 split)
__device__ __nv_bfloat16 g_al[(size_t)M_TOT * DIM];

// ---------------- helpers ----------------
__device__ __forceinline__ uint32_t smem_u32(const void* p) {
    uint32_t a;
    asm("{ .reg .u64 t; cvta.to.shared.u64 t, %1; cvt.u32.u64 %0, t; }"
        : "=r"(a) : "l"(p));
    return a;
}
__device__ __forceinline__ void ldmatrix_x4(uint32_t* r, uint32_t addr) {
    asm volatile("ldmatrix.sync.aligned.m8n8.x4.shared.b16 {%0,%1,%2,%3}, [%4];"
                 : "=r"(r[0]), "=r"(r[1]), "=r"(r[2]), "=r"(r[3]) : "r"(addr));
}
__device__ __forceinline__ void ldmatrix_x2(uint32_t* r, uint32_t addr) {
    asm volatile("ldmatrix.sync.aligned.m8n8.x2.shared.b16 {%0,%1}, [%2];"
                 : "=r"(r[0]), "=r"(r[1]) : "r"(addr));
}
__device__ __forceinline__ void ldmatrix_x2_trans(uint32_t* r, uint32_t addr) {
    asm volatile("ldmatrix.sync.aligned.m8n8.x2.trans.shared.b16 {%0,%1}, [%2];"
                 : "=r"(r[0]), "=r"(r[1]) : "r"(addr));
}
__device__ __forceinline__ void mma_bf16(float* c, const uint32_t* a, const uint32_t* b) {
    asm volatile("mma.sync.aligned.m16n8k16.row.col.f32.bf16.bf16.f32 "
                 "{%0,%1,%2,%3}, {%4,%5,%6,%7}, {%8,%9}, {%0,%1,%2,%3};"
                 : "+f"(c[0]), "+f"(c[1]), "+f"(c[2]), "+f"(c[3])
                 : "r"(a[0]), "r"(a[1]), "r"(a[2]), "r"(a[3]), "r"(b[0]), "r"(b[1]));
}
__device__ __forceinline__ void split2(float x, float y, uint32_t& hi, uint32_t& lo) {
    __nv_bfloat162 h;
    h.x = __float2bfloat16(x);
    h.y = __float2bfloat16(y);
    __nv_bfloat162 l;
    l.x = __float2bfloat16(x - __bfloat162float(h.x));
    l.y = __float2bfloat16(y - __bfloat162float(h.y));
    hi = *(uint32_t*)&h;
    lo = *(uint32_t*)&l;
}

#define CPASYNC(dst, src) \
    asm volatile("cp.async.cg.shared.global [%0], [%1], 16;" \
                 :: "r"(dst), "l"(src) : "memory")
#define CPCOMMIT() asm volatile("cp.async.commit_group;" ::: "memory")
#define CPWAIT1()  asm volatile("cp.async.wait_group 1;" ::: "memory")
#define CPWAIT0()  asm volatile("cp.async.wait_group 0;" ::: "memory")

// 64B-row tile (32 bf16), chunk^((row>>1)&3) swizzle — GEMM BK=32 tiles
__device__ __forceinline__ uint32_t tile_off(int row, int chunk) {
    return (uint32_t)(row * 64 + 16 * (chunk ^ ((row >> 1) & 3)));
}
// 128B-row tile (64 bf16), chunk^(row&7) swizzle — flash Q/K/V tiles
__device__ __forceinline__ uint32_t foff(int row, int chunk) {
    return (uint32_t)(row * 128 + 16 * (chunk ^ (row & 7)));
}

// ---------------- conversion kernels ----------------
__global__ void split_f32(const float* __restrict__ in,
                          __nv_bfloat16* __restrict__ hi,
                          __nv_bfloat16* __restrict__ lo, int n)
{
    int i = blockIdx.x * 256 + threadIdx.x;
    if (i < n) {
        float v = in[i];
        __nv_bfloat16 h = __float2bfloat16(v);
        hi[i] = h;
        lo[i] = __float2bfloat16(v - __bfloat162float(h));
    }
}
__global__ void splitT_f32(const float* __restrict__ w,
                           __nv_bfloat16* __restrict__ hiT,
                           __nv_bfloat16* __restrict__ loT, int K, int N)
{
    int i = blockIdx.x * 256 + threadIdx.x;
    if (i < K * N) {
        int k = i / N, n = i - k * N;
        float v = w[i];
        __nv_bfloat16 h = __float2bfloat16(v);
        hiT[(size_t)n * K + k] = h;
        loT[(size_t)n * K + k] = __float2bfloat16(v - __bfloat162float(h));
    }
}

// ---------------- mma.sync split-bf16 GEMM (cp.async 3-stage) ----------------
// C[M,N] = A[M,K] @ B^T[N,K] + bias. CTA 128x128, BK=32, 8 warps, warp 64x32.
// smem stage: [Ah 8K][Al 8K][Bh 8K][Bl 8K] = 32KB; 3 stages = 96KB dynamic.
#define GS_STAGE 32768
#define GS_AL    8192
#define GS_BH    16384
#define GS_BL    24576
#define GEMM_SMEM (3 * GS_STAGE)

template <bool QKV>
__global__ __launch_bounds__(256, 2)
void gemm_mma(const __nv_bfloat16* __restrict__ Ah, const __nv_bfloat16* __restrict__ Al,
              const __nv_bfloat16* __restrict__ Bh, const __nv_bfloat16* __restrict__ Bl,
              const float* __restrict__ bias, float* __restrict__ Cout,
              int Ntot, int Ktot)
{
    extern __shared__ char gs[];
    const uint32_t sb = smem_u32(gs);

    const int tid  = threadIdx.x;
    const int lane = tid & 31;
    const int wid  = tid >> 5;
    const int wm   = wid >> 2;
    const int wn   = wid & 3;
    const int m0   = blockIdx.y * 128;
    const int n0   = blockIdx.x * 128;

    float c[4][4][4];
    #pragma unroll
    for (int i = 0; i < 4; ++i)
        #pragma unroll
        for (int j = 0; j < 4; ++j)
            #pragma unroll
            for (int t = 0; t < 4; ++t) c[i][j][t] = 0.f;

    auto load_stage = [&](int stage, int k0) {
        const uint32_t s0 = sb + stage * GS_STAGE;
        #pragma unroll
        for (int it = 0; it < 2; ++it) {
            const int idx = it * 256 + tid;
            const int row = idx >> 2;
            const int cc  = idx & 3;
            const uint32_t so = tile_off(row, cc);
            const size_t ga = (size_t)(m0 + row) * Ktot + k0 + cc * 8;
            const size_t gb = (size_t)(n0 + row) * Ktot + k0 + cc * 8;
            CPASYNC(s0 + so,         Ah + ga);
            CPASYNC(s0 + GS_AL + so, Al + ga);
            CPASYNC(s0 + GS_BH + so, Bh + gb);
            CPASYNC(s0 + GS_BL + so, Bl + gb);
        }
        CPCOMMIT();
    };

    const int nk = Ktot / 32;        // 20 for both gemms
    load_stage(0, 0);
    load_stage(1, 32);

    int st = 0;
    for (int ki = 0; ki < nk; ++ki) {
        if (ki + 2 <= nk) { CPWAIT1(); } else { CPWAIT0(); }
        __syncthreads();
        if (ki + 2 < nk) {
            int st2 = st + 2; if (st2 >= 3) st2 -= 3;
            load_stage(st2, (ki + 2) * 32);
        }

        const uint32_t s0 = sb + st * GS_STAGE;
        #pragma unroll
        for (int ks = 0; ks < 2; ++ks) {
            uint32_t bh[4][2], bl[4][2];
            const int lr = lane & 7;
            const int lc = (lane >> 3) & 1;
            #pragma unroll
            for (int ni = 0; ni < 4; ++ni) {
                const int r = wn * 32 + ni * 8 + lr;
                const uint32_t off = tile_off(r, ks * 2 + lc);
                ldmatrix_x2(bh[ni], s0 + GS_BH + off);
                ldmatrix_x2(bl[ni], s0 + GS_BL + off);
            }
            #pragma unroll
            for (int mi = 0; mi < 4; ++mi) {
                uint32_t ah[4], al[4];
                const int r = wm * 64 + mi * 16 + (lane & 15);
                const uint32_t off = tile_off(r, ks * 2 + (lane >> 4));
                ldmatrix_x4(ah, s0 + off);
                ldmatrix_x4(al, s0 + GS_AL + off);
                #pragma unroll
                for (int ni = 0; ni < 4; ++ni) {
                    mma_bf16(c[mi][ni], ah, bh[ni]);
                    mma_bf16(c[mi][ni], ah, bl[ni]);
                    mma_bf16(c[mi][ni], al, bh[ni]);
                }
            }
        }
        if (++st >= 3) st = 0;
    }

    #pragma unroll
    for (int mi = 0; mi < 4; ++mi) {
        #pragma unroll
        for (int ni = 0; ni < 4; ++ni) {
            const int r0  = m0 + wm * 64 + mi * 16 + (lane >> 2);
            const int col = n0 + wn * 32 + ni * 8 + (lane & 3) * 2;
            const float b0 = bias[col], b1 = bias[col + 1];
            #pragma unroll
            for (int half = 0; half < 2; ++half) {
                const int r = r0 + half * 8;
                const float vx = c[mi][ni][half * 2 + 0] + b0;
                const float vy = c[mi][ni][half * 2 + 1] + b1;
                if (QKV) {
                    const int bb  = r >> 10;
                    const int iq  = r & 1023;
                    const int sel = col / DIM;
                    const int nc  = col - sel * DIM;
                    const int h   = nc >> 6;
                    const int d   = nc & 63;
                    __nv_bfloat16* dh = (sel == 0) ? g_qh : (sel == 1) ? g_kh : g_vh;
                    __nv_bfloat16* dl = (sel == 0) ? g_ql : (sel == 1) ? g_kl : g_vl;
                    const size_t idx = (((size_t)(bb * HEADS + h)) * SEQ + iq) * HD + d;
                    uint32_t hi, lo;
                    split2(vx, vy, hi, lo);
                    *(uint32_t*)(dh + idx) = hi;
                    *(uint32_t*)(dl + idx) = lo;
                } else {
                    float2 v; v.x = vx; v.y = vy;
                    *(float2*)&Cout[(size_t)r * Ntot + col] = v;
                }
            }
        }
    }
}

// ---------------- flash attention with mma.sync (cp.async 2-stage K/V) ----------------
// grid (SEQ/128, B*HEADS), 256 thr. Q resident 32KB; K/V stages 2x32KB = 96KB.
// Single __syncthreads per key-block; 2 CTAs/SM forced.
#define FQH 0
#define FQL 16384
#define FKV 32768
#define FKV_STRIDE 32768
#define FKL_O 8192
#define FVH_O 16384
#define FVL_O 24576
#define FLASH_SMEM (32768 + 2 * FKV_STRIDE)   // 98304

__global__ __launch_bounds__(256, 2)
void flash_mma()
{
    extern __shared__ char fs[];
    const uint32_t sb = smem_u32(fs);
    const int tid  = threadIdx.x;
    const int lane = tid & 31;
    const int wid  = tid >> 5;
    const int bh   = blockIdx.y;
    const int q0   = blockIdx.x * 128;
    const size_t base = (size_t)bh * SEQ * HD;

    auto load_kv = [&](int stage, int kb) {
        const uint32_t s0 = sb + FKV + stage * FKV_STRIDE;
        #pragma unroll
        for (int i = 0; i < 2; ++i) {
            const int idx = i * 256 + tid;     // 0..511
            const int row = idx >> 3, ch = idx & 7;
            const uint32_t so = foff(row, ch);
            const size_t g = base + (size_t)(kb + row) * HD + ch * 8;
            CPASYNC(s0 + so,         g_kh + g);
            CPASYNC(s0 + FKL_O + so, g_kl + g);
            CPASYNC(s0 + FVH_O + so, g_vh + g);
            CPASYNC(s0 + FVL_O + so, g_vl + g);
        }
        CPCOMMIT();
    };

    // start first K/V load, then stage Q while it flies
    load_kv(0, 0);
    #pragma unroll
    for (int i = 0; i < 4; ++i) {
        const int idx = i * 256 + tid;         // 0..1023
        const int row = idx >> 3, ch = idx & 7;
        const uint32_t so = foff(row, ch);
        const size_t g = base + (size_t)(q0 + row) * HD + ch * 8;
        *(uint4*)(fs + FQH + so) = *(const uint4*)(g_qh + g);
        *(uint4*)(fs + FQL + so) = *(const uint4*)(g_ql + g);
    }

    float O[8][4];
    #pragma unroll
    for (int i = 0; i < 8; ++i)
        #pragma unroll
        for (int t = 0; t < 4; ++t) O[i][t] = 0.f;
    float m0 = -1e30f, m1 = -1e30f, l0 = 0.f, l1 = 0.f;

    const int nkb = SEQ / 64;
    for (int kbi = 0; kbi < nkb; ++kbi) {
        CPWAIT0();
        __syncthreads();
        // prefetch next K/V block into the other stage (its data was consumed
        // in iteration kbi-1; the barrier above proves all warps are done).
        if (kbi + 1 < nkb) load_kv((kbi + 1) & 1, (kbi + 1) * 64);

        const uint32_t s0 = sb + FKV + (kbi & 1) * FKV_STRIDE;

        // S = Q K^T  (128x64 per CTA; 16x64 per warp)
        float c[8][4];
        #pragma unroll
        for (int i = 0; i < 8; ++i)
            #pragma unroll
            for (int t = 0; t < 4; ++t) c[i][t] = 0.f;

        #pragma unroll
        for (int ks = 0; ks < 4; ++ks) {
            uint32_t qh[4], ql[4];
            {
                const int r  = wid * 16 + (lane & 15);
                const int ch = ks * 2 + (lane >> 4);
                ldmatrix_x4(qh, sb + FQH + foff(r, ch));
                ldmatrix_x4(ql, sb + FQL + foff(r, ch));
            }
            const int lr = lane & 7;
            const int lc = (lane >> 3) & 1;
            #pragma unroll
            for (int ni = 0; ni < 8; ++ni) {
                uint32_t bh2[2], bl2[2];
                const uint32_t off = foff(ni * 8 + lr, ks * 2 + lc);
                ldmatrix_x2(bh2, s0 + off);
                ldmatrix_x2(bl2, s0 + FKL_O + off);
                mma_bf16(c[ni], qh, bh2);
                mma_bf16(c[ni], qh, bl2);
                mma_bf16(c[ni], ql, bh2);
            }
        }

        // scale + online softmax
        float rm0 = -1e30f, rm1 = -1e30f;
        #pragma unroll
        for (int ni = 0; ni < 8; ++ni) {
            #pragma unroll
            for (int t = 0; t < 4; ++t) c[ni][t] *= ATT_SCALE;
            rm0 = fmaxf(rm0, fmaxf(c[ni][0], c[ni][1]));
            rm1 = fmaxf(rm1, fmaxf(c[ni][2], c[ni][3]));
        }
        #pragma unroll
        for (int off = 1; off < 4; off <<= 1) {
            rm0 = fmaxf(rm0, __shfl_xor_sync(0xffffffffu, rm0, off));
            rm1 = fmaxf(rm1, __shfl_xor_sync(0xffffffffu, rm1, off));
        }
        const float mn0 = fmaxf(m0, rm0), mn1 = fmaxf(m1, rm1);
        const float cor0 = __expf(m0 - mn0), cor1 = __expf(m1 - mn1);
        m0 = mn0; m1 = mn1;

        float rs0 = 0.f, rs1 = 0.f;
        #pragma unroll
        for (int ni = 0; ni < 8; ++ni) {
            c[ni][0] = __expf(c[ni][0] - m0);
            c[ni][1] = __expf(c[ni][1] - m0);
            c[ni][2] = __expf(c[ni][2] - m1);
            c[ni][3] = __expf(c[ni][3] - m1);
            rs0 += c[ni][0] + c[ni][1];
            rs1 += c[ni][2] + c[ni][3];
        }
        #pragma unroll
        for (int off = 1; off < 4; off <<= 1) {
            rs0 += __shfl_xor_sync(0xffffffffu, rs0, off);
            rs1 += __shfl_xor_sync(0xffffffffu, rs1, off);
        }
        l0 = l0 * cor0 + rs0;
        l1 = l1 * cor1 + rs1;
        #pragma unroll
        for (int nd = 0; nd < 8; ++nd) {
            O[nd][0] *= cor0; O[nd][1] *= cor0;
            O[nd][2] *= cor1; O[nd][3] *= cor1;
        }

        // O += P V
        #pragma unroll
        for (int ks2 = 0; ks2 < 4; ++ks2) {
            uint32_t ph[4], pl[4];
            split2(c[2*ks2][0],   c[2*ks2][1],   ph[0], pl[0]);
            split2(c[2*ks2][2],   c[2*ks2][3],   ph[1], pl[1]);
            split2(c[2*ks2+1][0], c[2*ks2+1][1], ph[2], pl[2]);
            split2(c[2*ks2+1][2], c[2*ks2+1][3], ph[3], pl[3]);
            const int vr = ks2 * 16 + (lane & 15);
            #pragma unroll
            for (int nd = 0; nd < 8; ++nd) {
                uint32_t vh2[2], vl2[2];
                const uint32_t off = foff(vr, nd);
                ldmatrix_x2_trans(vh2, s0 + FVH_O + off);
                ldmatrix_x2_trans(vl2, s0 + FVL_O + off);
                mma_bf16(O[nd], ph, vh2);
                mma_bf16(O[nd], ph, vl2);
                mma_bf16(O[nd], pl, vh2);
            }
        }
    }

    // epilogue
    const float inv0 = 1.f / l0, inv1 = 1.f / l1;
    const int b = bh / HEADS;
    const int h = bh - b * HEADS;
    const int r0 = q0 + wid * 16 + (lane >> 2);
    #pragma unroll
    for (int nd = 0; nd < 8; ++nd) {
        const int col = h * HD + nd * 8 + (lane & 3) * 2;
        uint32_t hi, lo;
        split2(O[nd][0] * inv0, O[nd][1] * inv0, hi, lo);
        size_t idx = ((size_t)(b * SEQ + r0)) * DIM + col;
        *(uint32_t*)(g_ah + idx) = hi;
        *(uint32_t*)(g_al + idx) = lo;
        split2(O[nd][2] * inv1, O[nd][3] * inv1, hi, lo);
        idx = ((size_t)(b * SEQ + r0 + 8)) * DIM + col;
        *(uint32_t*)(g_ah + idx) = hi;
        *(uint32_t*)(g_al + idx) = lo;
    }
}

// ---------------- launch ----------------
extern "C" void kernel_launch(void* const* d_in, const int* in_sizes, int n_in,
                              void* d_out, int out_size)
{
    const float* x     = (const float*)d_in[0];
    const float* w_qkv = (const float*)d_in[1];
    const float* b_qkv = (const float*)d_in[2];
    const float* w_out = (const float*)d_in[3];
    const float* b_out = (const float*)d_in[4];
    float* out = (float*)d_out;

    __nv_bfloat16 *xh, *xl, *wqh, *wql, *woh, *wol, *ah, *al;
    cudaGetSymbolAddress((void**)&xh,  g_xh);
    cudaGetSymbolAddress((void**)&xl,  g_xl);
    cudaGetSymbolAddress((void**)&wqh, g_wqh);
    cudaGetSymbolAddress((void**)&wql, g_wql);
    cudaGetSymbolAddress((void**)&woh, g_woh);
    cudaGetSymbolAddress((void**)&wol, g_wol);
    cudaGetSymbolAddress((void**)&ah,  g_ah);
    cudaGetSymbolAddress((void**)&al,  g_al);

    cudaFuncSetAttribute(gemm_mma<true>,  cudaFuncAttributeMaxDynamicSharedMemorySize, GEMM_SMEM);
    cudaFuncSetAttribute(gemm_mma<false>, cudaFuncAttributeMaxDynamicSharedMemorySize, GEMM_SMEM);
    cudaFuncSetAttribute(flash_mma, cudaFuncAttributeMaxDynamicSharedMemorySize, FLASH_SMEM);

    // 0) fp32 -> bf16 hi/lo splits
    const int nx = M_TOT * DIM;
    split_f32<<<(nx + 255) / 256, 256>>>(x, xh, xl, nx);
    splitT_f32<<<(DIM * QKV_N + 255) / 256, 256>>>(w_qkv, wqh, wql, DIM, QKV_N);
    splitT_f32<<<(DIM * DIM + 255) / 256, 256>>>(w_out, woh, wol, DIM, DIM);

    // 1) QKV GEMM -> per-head bf16 hi/lo q/k/v
    gemm_mma<true><<<dim3(QKV_N / 128, M_TOT / 128), 256, GEMM_SMEM>>>(
        xh, xl, wqh, wql, b_qkv, nullptr, QKV_N, DIM);

    // 2) flash attention (HMMA) -> g_ah/g_al
    flash_mma<<<dim3(SEQ / 128, B_SZ * HEADS), 256, FLASH_SMEM>>>();

    // 3) out projection (HMMA) -> d_out
    gemm_mma<false><<<dim3(DIM / 128, M_TOT / 128), 256, GEMM_SMEM>>>(
        ah, al, woh, wol, b_out, out, DIM, DIM);
}

// round 7
// speedup vs baseline: 4.0125x; 1.0285x over previous
#include <cuda_runtime.h>
#include <cuda_bf16.h>
#include <cstdint>

#define DIM     640
#define HEADS   10
#define HD      64
#define B_SZ    16
#define SEQ     1024
#define M_TOT   (B_SZ * SEQ)     // 16384
#define QKV_N   (3 * DIM)        // 1920
#define ATT_SCALE 0.0395284707521047416f   // 640^-0.5

// ---------------- scratch (device globals) ----------------
__device__ __nv_bfloat16 g_xh[(size_t)M_TOT * DIM];
__device__ __nv_bfloat16 g_xl[(size_t)M_TOT * DIM];
__device__ __nv_bfloat16 g_wqh[(size_t)DIM * QKV_N];   // w_qkv hi  [640][1920] natural
__device__ __nv_bfloat16 g_wql[(size_t)DIM * QKV_N];
__device__ __nv_bfloat16 g_woh[(size_t)DIM * DIM];     // w_out hi  [640][640] natural
__device__ __nv_bfloat16 g_wol[(size_t)DIM * DIM];
// per-head q/k/v, bf16 hi/lo: [B*HEADS][SEQ][64]
__device__ __nv_bfloat16 g_qh[(size_t)B_SZ * HEADS * SEQ * HD];
__device__ __nv_bfloat16 g_ql[(size_t)B_SZ * HEADS * SEQ * HD];
__device__ __nv_bfloat16 g_kh[(size_t)B_SZ * HEADS * SEQ * HD];
__device__ __nv_bfloat16 g_kl[(size_t)B_SZ * HEADS * SEQ * HD];
__device__ __nv_bfloat16 g_vh[(size_t)B_SZ * HEADS * SEQ * HD];
__device__ __nv_bfloat16 g_vl[(size_t)B_SZ * HEADS * SEQ * HD];
__device__ __nv_bfloat16 g_ah[(size_t)M_TOT * DIM];    // attention out hi (bf16 split)
__device__ __nv_bfloat16 g_al[(size_t)M_TOT * DIM];

// ---------------- helpers ----------------
__device__ __forceinline__ uint32_t smem_u32(const void* p) {
    uint32_t a;
    asm("{ .reg .u64 t; cvta.to.shared.u64 t, %1; cvt.u32.u64 %0, t; }"
        : "=r"(a) : "l"(p));
    return a;
}
__device__ __forceinline__ void ldmatrix_x4(uint32_t* r, uint32_t addr) {
    asm volatile("ldmatrix.sync.aligned.m8n8.x4.shared.b16 {%0,%1,%2,%3}, [%4];"
                 : "=r"(r[0]), "=r"(r[1]), "=r"(r[2]), "=r"(r[3]) : "r"(addr));
}
__device__ __forceinline__ void ldmatrix_x4_trans(uint32_t* r, uint32_t addr) {
    asm volatile("ldmatrix.sync.aligned.m8n8.x4.trans.shared.b16 {%0,%1,%2,%3}, [%4];"
                 : "=r"(r[0]), "=r"(r[1]), "=r"(r[2]), "=r"(r[3]) : "r"(addr));
}
__device__ __forceinline__ void mma_bf16(float* c, const uint32_t* a, const uint32_t* b) {
    asm volatile("mma.sync.aligned.m16n8k16.row.col.f32.bf16.bf16.f32 "
                 "{%0,%1,%2,%3}, {%4,%5,%6,%7}, {%8,%9}, {%0,%1,%2,%3};"
                 : "+f"(c[0]), "+f"(c[1]), "+f"(c[2]), "+f"(c[3])
                 : "r"(a[0]), "r"(a[1]), "r"(a[2]), "r"(a[3]), "r"(b[0]), "r"(b[1]));
}
__device__ __forceinline__ void split2(float x, float y, uint32_t& hi, uint32_t& lo) {
    __nv_bfloat162 h;
    h.x = __float2bfloat16(x);
    h.y = __float2bfloat16(y);
    __nv_bfloat162 l;
    l.x = __float2bfloat16(x - __bfloat162float(h.x));
    l.y = __float2bfloat16(y - __bfloat162float(h.y));
    hi = *(uint32_t*)&h;
    lo = *(uint32_t*)&l;
}

#define CPASYNC(dst, src) \
    asm volatile("cp.async.cg.shared.global [%0], [%1], 16;" \
                 :: "r"(dst), "l"(src) : "memory")
#define CPCOMMIT() asm volatile("cp.async.commit_group;" ::: "memory")
#define CPWAIT1()  asm volatile("cp.async.wait_group 1;" ::: "memory")
#define CPWAIT0()  asm volatile("cp.async.wait_group 0;" ::: "memory")

// 64B-row tile (32 bf16), chunk^((row>>1)&3) swizzle — GEMM A tiles (BK=32)
__device__ __forceinline__ uint32_t tile_off(int row, int chunk) {
    return (uint32_t)(row * 64 + 16 * (chunk ^ ((row >> 1) & 3)));
}
// 256B-row tile (128 bf16), chunk^(row&7) swizzle — GEMM B tiles [32k][128n]
__device__ __forceinline__ uint32_t boff(int row, int chunk) {
    return (uint32_t)(row * 256 + 16 * (chunk ^ (row & 7)));
}
// 128B-row tile (64 bf16), chunk^(row&7) swizzle — flash Q/K/V tiles
__device__ __forceinline__ uint32_t foff(int row, int chunk) {
    return (uint32_t)(row * 128 + 16 * (chunk ^ (row & 7)));
}

// ---------------- conversion kernel (natural layout, coalesced) ----------------
__global__ void split_f32(const float* __restrict__ in,
                          __nv_bfloat16* __restrict__ hi,
                          __nv_bfloat16* __restrict__ lo, int n)
{
    int i = blockIdx.x * 256 + threadIdx.x;
    if (i < n) {
        float v = in[i];
        __nv_bfloat16 h = __float2bfloat16(v);
        hi[i] = h;
        lo[i] = __float2bfloat16(v - __bfloat162float(h));
    }
}

// ---------------- mma.sync split-bf16 GEMM (cp.async 3-stage) ----------------
// C[M,N] = A[M,K] @ W[K,N] + bias. A hi/lo [M][K]; W hi/lo [K][N] natural.
// CTA 128x128, BK=32, 8 warps (2x4), warp 64x32.
// stage: [Ah 8K][Al 8K][Bh 8K][Bl 8K] = 32KB; 3 stages = 96KB dynamic.
// B tile: [32 k][128 n], 256B rows, boff swizzle, read with ldmatrix.x4.trans
// (lanes 0-15: hi k-rows, lanes 16-31: lo k-rows -> one x4 = hi+lo frags).
#define GS_STAGE 32768
#define GS_AL    8192
#define GS_BH    16384
#define GS_BL    24576
#define GEMM_SMEM (3 * GS_STAGE)

template <bool QKV>
__global__ __launch_bounds__(256, 2)
void gemm_mma(const __nv_bfloat16* __restrict__ Ah, const __nv_bfloat16* __restrict__ Al,
              const __nv_bfloat16* __restrict__ Bh, const __nv_bfloat16* __restrict__ Bl,
              const float* __restrict__ bias, float* __restrict__ Cout,
              int Ntot, int Ktot)
{
    extern __shared__ char gs[];
    const uint32_t sb = smem_u32(gs);

    const int tid  = threadIdx.x;
    const int lane = tid & 31;
    const int wid  = tid >> 5;
    const int wm   = wid >> 2;
    const int wn   = wid & 3;
    const int m0   = blockIdx.y * 128;
    const int n0   = blockIdx.x * 128;

    float c[4][4][4];
    #pragma unroll
    for (int i = 0; i < 4; ++i)
        #pragma unroll
        for (int j = 0; j < 4; ++j)
            #pragma unroll
            for (int t = 0; t < 4; ++t) c[i][j][t] = 0.f;

    auto load_stage = [&](int stage, int k0) {
        const uint32_t s0 = sb + stage * GS_STAGE;
        // A: [128 m][32 k] hi/lo, 512 chunks each, 2 per thread
        #pragma unroll
        for (int it = 0; it < 2; ++it) {
            const int idx = it * 256 + tid;
            const int row = idx >> 2;            // m row
            const int cc  = idx & 3;             // k chunk (8 bf16)
            const uint32_t so = tile_off(row, cc);
            const size_t ga = (size_t)(m0 + row) * Ktot + k0 + cc * 8;
            CPASYNC(s0 + so,         Ah + ga);
            CPASYNC(s0 + GS_AL + so, Al + ga);
        }
        // B: [32 k][128 n] hi/lo, 512 chunks each, 2 per thread
        #pragma unroll
        for (int it = 0; it < 2; ++it) {
            const int idx = it * 256 + tid;
            const int row = idx >> 4;            // k row (0..31)
            const int cc  = idx & 15;            // n chunk (8 bf16)
            const uint32_t so = boff(row, cc);
            const size_t gb = (size_t)(k0 + row) * Ntot + n0 + cc * 8;
            CPASYNC(s0 + GS_BH + so, Bh + gb);
            CPASYNC(s0 + GS_BL + so, Bl + gb);
        }
        CPCOMMIT();
    };

    const int nk = Ktot / 32;        // 20 for both gemms
    load_stage(0, 0);
    load_stage(1, 32);

    const int hilo_b = (lane >> 4) * (GS_BL - GS_BH);  // 0 for hi lanes, 8192 for lo
    const int krow_b = lane & 15;

    int st = 0;
    for (int ki = 0; ki < nk; ++ki) {
        if (ki + 2 <= nk) { CPWAIT1(); } else { CPWAIT0(); }
        __syncthreads();
        if (ki + 2 < nk) {
            int st2 = st + 2; if (st2 >= 3) st2 -= 3;
            load_stage(st2, (ki + 2) * 32);
        }

        const uint32_t s0 = sb + st * GS_STAGE;
        #pragma unroll
        for (int ks = 0; ks < 2; ++ks) {
            // B frags: one x4.trans per ni -> b[0..1]=hi, b[2..3]=lo
            uint32_t b4[4][4];
            #pragma unroll
            for (int ni = 0; ni < 4; ++ni) {
                const int chn = wn * 4 + ni;     // n chunk of this warp/ni
                ldmatrix_x4_trans(b4[ni],
                    s0 + GS_BH + hilo_b + boff(ks * 16 + krow_b, chn));
            }
            #pragma unroll
            for (int mi = 0; mi < 4; ++mi) {
                uint32_t ah[4], al[4];
                const int r = wm * 64 + mi * 16 + (lane & 15);
                const uint32_t off = tile_off(r, ks * 2 + (lane >> 4));
                ldmatrix_x4(ah, s0 + off);
                ldmatrix_x4(al, s0 + GS_AL + off);
                #pragma unroll
                for (int ni = 0; ni < 4; ++ni) {
                    mma_bf16(c[mi][ni], ah, b4[ni] + 0);
                    mma_bf16(c[mi][ni], ah, b4[ni] + 2);
                    mma_bf16(c[mi][ni], al, b4[ni] + 0);
                }
            }
        }
        if (++st >= 3) st = 0;
    }

    #pragma unroll
    for (int mi = 0; mi < 4; ++mi) {
        #pragma unroll
        for (int ni = 0; ni < 4; ++ni) {
            const int r0  = m0 + wm * 64 + mi * 16 + (lane >> 2);
            const int col = n0 + wn * 32 + ni * 8 + (lane & 3) * 2;
            const float b0 = bias[col], b1 = bias[col + 1];
            #pragma unroll
            for (int half = 0; half < 2; ++half) {
                const int r = r0 + half * 8;
                const float vx = c[mi][ni][half * 2 + 0] + b0;
                const float vy = c[mi][ni][half * 2 + 1] + b1;
                if (QKV) {
                    const int bb  = r >> 10;
                    const int iq  = r & 1023;
                    const int sel = col / DIM;
                    const int nc  = col - sel * DIM;
                    const int h   = nc >> 6;
                    const int d   = nc & 63;
                    __nv_bfloat16* dh = (sel == 0) ? g_qh : (sel == 1) ? g_kh : g_vh;
                    __nv_bfloat16* dl = (sel == 0) ? g_ql : (sel == 1) ? g_kl : g_vl;
                    const size_t idx = (((size_t)(bb * HEADS + h)) * SEQ + iq) * HD + d;
                    uint32_t hi, lo;
                    split2(vx, vy, hi, lo);
                    *(uint32_t*)(dh + idx) = hi;
                    *(uint32_t*)(dl + idx) = lo;
                } else {
                    float2 v; v.x = vx; v.y = vy;
                    *(float2*)&Cout[(size_t)r * Ntot + col] = v;
                }
            }
        }
    }
}

// ---------------- flash attention with mma.sync (cp.async 2-stage K/V) ----------------
// grid (SEQ/128, B*HEADS), 256 thr. Q resident 32KB; K/V stages 2x32KB = 96KB.
// hi/lo K and V frags fetched with single x4 ldmatrix (lanes 16-31 -> lo region).
#define FQH 0
#define FQL 16384
#define FKV 32768
#define FKV_STRIDE 32768
#define FKL_O 8192
#define FVH_O 16384
#define FVL_O 24576
#define FLASH_SMEM (32768 + 2 * FKV_STRIDE)   // 98304

__global__ __launch_bounds__(256, 2)
void flash_mma()
{
    extern __shared__ char fs[];
    const uint32_t sb = smem_u32(fs);
    const int tid  = threadIdx.x;
    const int lane = tid & 31;
    const int wid  = tid >> 5;
    const int bh   = blockIdx.y;
    const int q0   = blockIdx.x * 128;
    const size_t base = (size_t)bh * SEQ * HD;

    auto load_kv = [&](int stage, int kb) {
        const uint32_t s0 = sb + FKV + stage * FKV_STRIDE;
        #pragma unroll
        for (int i = 0; i < 2; ++i) {
            const int idx = i * 256 + tid;     // 0..511
            const int row = idx >> 3, ch = idx & 7;
            const uint32_t so = foff(row, ch);
            const size_t g = base + (size_t)(kb + row) * HD + ch * 8;
            CPASYNC(s0 + so,         g_kh + g);
            CPASYNC(s0 + FKL_O + so, g_kl + g);
            CPASYNC(s0 + FVH_O + so, g_vh + g);
            CPASYNC(s0 + FVL_O + so, g_vl + g);
        }
        CPCOMMIT();
    };

    // start first K/V load, then stage Q while it flies
    load_kv(0, 0);
    #pragma unroll
    for (int i = 0; i < 4; ++i) {
        const int idx = i * 256 + tid;         // 0..1023
        const int row = idx >> 3, ch = idx & 7;
        const uint32_t so = foff(row, ch);
        const size_t g = base + (size_t)(q0 + row) * HD + ch * 8;
        *(uint4*)(fs + FQH + so) = *(const uint4*)(g_qh + g);
        *(uint4*)(fs + FQL + so) = *(const uint4*)(g_ql + g);
    }

    float O[8][4];
    #pragma unroll
    for (int i = 0; i < 8; ++i)
        #pragma unroll
        for (int t = 0; t < 4; ++t) O[i][t] = 0.f;
    float m0 = -1e30f, m1 = -1e30f, l0 = 0.f, l1 = 0.f;

    const int hilo_k = (lane >> 4) * FKL_O;            // K: +8192 for lo lanes
    const int hilo_v = (lane >> 4) * (FVL_O - FVH_O);  // V: +8192 for lo lanes

    const int nkb = SEQ / 64;
    for (int kbi = 0; kbi < nkb; ++kbi) {
        CPWAIT0();
        __syncthreads();
        if (kbi + 1 < nkb) load_kv((kbi + 1) & 1, (kbi + 1) * 64);

        const uint32_t s0 = sb + FKV + (kbi & 1) * FKV_STRIDE;

        // S = Q K^T  (128x64 per CTA; 16x64 per warp)
        float c[8][4];
        #pragma unroll
        for (int i = 0; i < 8; ++i)
            #pragma unroll
            for (int t = 0; t < 4; ++t) c[i][t] = 0.f;

        #pragma unroll
        for (int ks = 0; ks < 4; ++ks) {
            uint32_t qh[4], ql[4];
            {
                const int r  = wid * 16 + (lane & 15);
                const int ch = ks * 2 + (lane >> 4);
                ldmatrix_x4(qh, sb + FQH + foff(r, ch));
                ldmatrix_x4(ql, sb + FQL + foff(r, ch));
            }
            const int lr2 = lane & 7;
            const int lc2 = (lane >> 3) & 1;
            #pragma unroll
            for (int ni = 0; ni < 8; ++ni) {
                // one x4: k-frag hi (r[0..1]) + lo (r[2..3])
                uint32_t kb4[4];
                ldmatrix_x4(kb4, s0 + hilo_k + foff(ni * 8 + lr2, ks * 2 + lc2));
                mma_bf16(c[ni], qh, kb4 + 0);
                mma_bf16(c[ni], qh, kb4 + 2);
                mma_bf16(c[ni], ql, kb4 + 0);
            }
        }

        // scale + online softmax
        float rm0 = -1e30f, rm1 = -1e30f;
        #pragma unroll
        for (int ni = 0; ni < 8; ++ni) {
            #pragma unroll
            for (int t = 0; t < 4; ++t) c[ni][t] *= ATT_SCALE;
            rm0 = fmaxf(rm0, fmaxf(c[ni][0], c[ni][1]));
            rm1 = fmaxf(rm1, fmaxf(c[ni][2], c[ni][3]));
        }
        #pragma unroll
        for (int off = 1; off < 4; off <<= 1) {
            rm0 = fmaxf(rm0, __shfl_xor_sync(0xffffffffu, rm0, off));
            rm1 = fmaxf(rm1, __shfl_xor_sync(0xffffffffu, rm1, off));
        }
        const float mn0 = fmaxf(m0, rm0), mn1 = fmaxf(m1, rm1);
        const float cor0 = __expf(m0 - mn0), cor1 = __expf(m1 - mn1);
        m0 = mn0; m1 = mn1;

        float rs0 = 0.f, rs1 = 0.f;
        #pragma unroll
        for (int ni = 0; ni < 8; ++ni) {
            c[ni][0] = __expf(c[ni][0] - m0);
            c[ni][1] = __expf(c[ni][1] - m0);
            c[ni][2] = __expf(c[ni][2] - m1);
            c[ni][3] = __expf(c[ni][3] - m1);
            rs0 += c[ni][0] + c[ni][1];
            rs1 += c[ni][2] + c[ni][3];
        }
        #pragma unroll
        for (int off = 1; off < 4; off <<= 1) {
            rs0 += __shfl_xor_sync(0xffffffffu, rs0, off);
            rs1 += __shfl_xor_sync(0xffffffffu, rs1, off);
        }
        l0 = l0 * cor0 + rs0;
        l1 = l1 * cor1 + rs1;
        #pragma unroll
        for (int nd = 0; nd < 8; ++nd) {
            O[nd][0] *= cor0; O[nd][1] *= cor0;
            O[nd][2] *= cor1; O[nd][3] *= cor1;
        }

        // O += P V
        #pragma unroll
        for (int ks2 = 0; ks2 < 4; ++ks2) {
            uint32_t ph[4], pl[4];
            split2(c[2*ks2][0],   c[2*ks2][1],   ph[0], pl[0]);
            split2(c[2*ks2][2],   c[2*ks2][3],   ph[1], pl[1]);
            split2(c[2*ks2+1][0], c[2*ks2+1][1], ph[2], pl[2]);
            split2(c[2*ks2+1][2], c[2*ks2+1][3], ph[3], pl[3]);
            const int vr = ks2 * 16 + (lane & 15);
            #pragma unroll
            for (int nd = 0; nd < 8; ++nd) {
                // one x4.trans: v-frag hi (r[0..1]) + lo (r[2..3])
                uint32_t vb4[4];
                ldmatrix_x4_trans(vb4, s0 + FVH_O + hilo_v + foff(vr, nd));
                mma_bf16(O[nd], ph, vb4 + 0);
                mma_bf16(O[nd], ph, vb4 + 2);
                mma_bf16(O[nd], pl, vb4 + 0);
            }
        }
    }

    // epilogue
    const float inv0 = 1.f / l0, inv1 = 1.f / l1;
    const int b = bh / HEADS;
    const int h = bh - b * HEADS;
    const int r0 = q0 + wid * 16 + (lane >> 2);
    #pragma unroll
    for (int nd = 0; nd < 8; ++nd) {
        const int col = h * HD + nd * 8 + (lane & 3) * 2;
        uint32_t hi, lo;
        split2(O[nd][0] * inv0, O[nd][1] * inv0, hi, lo);
        size_t idx = ((size_t)(b * SEQ + r0)) * DIM + col;
        *(uint32_t*)(g_ah + idx) = hi;
        *(uint32_t*)(g_al + idx) = lo;
        split2(O[nd][2] * inv1, O[nd][3] * inv1, hi, lo);
        idx = ((size_t)(b * SEQ + r0 + 8)) * DIM + col;
        *(uint32_t*)(g_ah + idx) = hi;
        *(uint32_t*)(g_al + idx) = lo;
    }
}

// ---------------- launch ----------------
extern "C" void kernel_launch(void* const* d_in, const int* in_sizes, int n_in,
                              void* d_out, int out_size)
{
    const float* x     = (const float*)d_in[0];
    const float* w_qkv = (const float*)d_in[1];
    const float* b_qkv = (const float*)d_in[2];
    const float* w_out = (const float*)d_in[3];
    const float* b_out = (const float*)d_in[4];
    float* out = (float*)d_out;

    __nv_bfloat16 *xh, *xl, *wqh, *wql, *woh, *wol, *ah, *al;
    cudaGetSymbolAddress((void**)&xh,  g_xh);
    cudaGetSymbolAddress((void**)&xl,  g_xl);
    cudaGetSymbolAddress((void**)&wqh, g_wqh);
    cudaGetSymbolAddress((void**)&wql, g_wql);
    cudaGetSymbolAddress((void**)&woh, g_woh);
    cudaGetSymbolAddress((void**)&wol, g_wol);
    cudaGetSymbolAddress((void**)&ah,  g_ah);
    cudaGetSymbolAddress((void**)&al,  g_al);

    cudaFuncSetAttribute(gemm_mma<true>,  cudaFuncAttributeMaxDynamicSharedMemorySize, GEMM_SMEM);
    cudaFuncSetAttribute(gemm_mma<false>, cudaFuncAttributeMaxDynamicSharedMemorySize, GEMM_SMEM);
    cudaFuncSetAttribute(flash_mma, cudaFuncAttributeMaxDynamicSharedMemorySize, FLASH_SMEM);

    // 0) fp32 -> bf16 hi/lo splits (ALL natural layout, coalesced)
    const int nx = M_TOT * DIM;
    split_f32<<<(nx + 255) / 256, 256>>>(x, xh, xl, nx);
    split_f32<<<(DIM * QKV_N + 255) / 256, 256>>>(w_qkv, wqh, wql, DIM * QKV_N);
    split_f32<<<(DIM * DIM + 255) / 256, 256>>>(w_out, woh, wol, DIM * DIM);

    // 1) QKV GEMM -> per-head bf16 hi/lo q/k/v
    gemm_mma<true><<<dim3(QKV_N / 128, M_TOT / 128), 256, GEMM_SMEM>>>(
        xh, xl, wqh, wql, b_qkv, nullptr, QKV_N, DIM);

    // 2) flash attention (HMMA) -> g_ah/g_al
    flash_mma<<<dim3(SEQ / 128, B_SZ * HEADS), 256, FLASH_SMEM>>>();

    // 3) out projection (HMMA) -> d_out
    gemm_mma<false><<<dim3(DIM / 128, M_TOT / 128), 256, GEMM_SMEM>>>(
        ah, al, woh, wol, b_out, out, DIM, DIM);
}

// round 8
// speedup vs baseline: 4.0224x; 1.0025x over previous
#include <cuda_runtime.h>
#include <cuda_bf16.h>
#include <cstdint>

#define DIM     640
#define HEADS   10
#define HD      64
#define B_SZ    16
#define SEQ     1024
#define M_TOT   (B_SZ * SEQ)     // 16384
#define QKV_N   (3 * DIM)        // 1920
#define ATT_SCALE 0.0395284707521047416f   // 640^-0.5

// ---------------- scratch (device globals) ----------------
__device__ __nv_bfloat16 g_xh[(size_t)M_TOT * DIM];
__device__ __nv_bfloat16 g_xl[(size_t)M_TOT * DIM];
__device__ __nv_bfloat16 g_wqh[(size_t)DIM * QKV_N];   // w_qkv hi  [640][1920] natural
__device__ __nv_bfloat16 g_wql[(size_t)DIM * QKV_N];
__device__ __nv_bfloat16 g_woh[(size_t)DIM * DIM];     // w_out hi  [640][640] natural
__device__ __nv_bfloat16 g_wol[(size_t)DIM * DIM];
// per-head q/k/v, bf16 hi/lo: [B*HEADS][SEQ][64]
__device__ __nv_bfloat16 g_qh[(size_t)B_SZ * HEADS * SEQ * HD];
__device__ __nv_bfloat16 g_ql[(size_t)B_SZ * HEADS * SEQ * HD];
__device__ __nv_bfloat16 g_kh[(size_t)B_SZ * HEADS * SEQ * HD];
__device__ __nv_bfloat16 g_kl[(size_t)B_SZ * HEADS * SEQ * HD];
__device__ __nv_bfloat16 g_vh[(size_t)B_SZ * HEADS * SEQ * HD];
__device__ __nv_bfloat16 g_vl[(size_t)B_SZ * HEADS * SEQ * HD];
__device__ __nv_bfloat16 g_ah[(size_t)M_TOT * DIM];    // attention out hi (bf16 split)
__device__ __nv_bfloat16 g_al[(size_t)M_TOT * DIM];

// ---------------- helpers ----------------
__device__ __forceinline__ uint32_t smem_u32(const void* p) {
    uint32_t a;
    asm("{ .reg .u64 t; cvta.to.shared.u64 t, %1; cvt.u32.u64 %0, t; }"
        : "=r"(a) : "l"(p));
    return a;
}
__device__ __forceinline__ void ldmatrix_x4(uint32_t* r, uint32_t addr) {
    asm volatile("ldmatrix.sync.aligned.m8n8.x4.shared.b16 {%0,%1,%2,%3}, [%4];"
                 : "=r"(r[0]), "=r"(r[1]), "=r"(r[2]), "=r"(r[3]) : "r"(addr));
}
__device__ __forceinline__ void ldmatrix_x4_trans(uint32_t* r, uint32_t addr) {
    asm volatile("ldmatrix.sync.aligned.m8n8.x4.trans.shared.b16 {%0,%1,%2,%3}, [%4];"
                 : "=r"(r[0]), "=r"(r[1]), "=r"(r[2]), "=r"(r[3]) : "r"(addr));
}
__device__ __forceinline__ void mma_bf16(float* c, const uint32_t* a, const uint32_t* b) {
    asm volatile("mma.sync.aligned.m16n8k16.row.col.f32.bf16.bf16.f32 "
                 "{%0,%1,%2,%3}, {%4,%5,%6,%7}, {%8,%9}, {%0,%1,%2,%3};"
                 : "+f"(c[0]), "+f"(c[1]), "+f"(c[2]), "+f"(c[3])
                 : "r"(a[0]), "r"(a[1]), "r"(a[2]), "r"(a[3]), "r"(b[0]), "r"(b[1]));
}
__device__ __forceinline__ void split2(float x, float y, uint32_t& hi, uint32_t& lo) {
    __nv_bfloat162 h;
    h.x = __float2bfloat16(x);
    h.y = __float2bfloat16(y);
    __nv_bfloat162 l;
    l.x = __float2bfloat16(x - __bfloat162float(h.x));
    l.y = __float2bfloat16(y - __bfloat162float(h.y));
    hi = *(uint32_t*)&h;
    lo = *(uint32_t*)&l;
}

#define CPASYNC(dst, src) \
    asm volatile("cp.async.cg.shared.global [%0], [%1], 16;" \
                 :: "r"(dst), "l"(src) : "memory")
#define CPCOMMIT() asm volatile("cp.async.commit_group;" ::: "memory")
#define CPWAIT1()  asm volatile("cp.async.wait_group 1;" ::: "memory")
#define CPWAIT0()  asm volatile("cp.async.wait_group 0;" ::: "memory")

// 64B-row tile (32 bf16), chunk^((row>>1)&3) swizzle — GEMM A tiles (BK=32)
__device__ __forceinline__ uint32_t tile_off(int row, int chunk) {
    return (uint32_t)(row * 64 + 16 * (chunk ^ ((row >> 1) & 3)));
}
// 256B-row tile (128 bf16), chunk^(row&7) swizzle — GEMM B tiles [32k][128n]
__device__ __forceinline__ uint32_t boff(int row, int chunk) {
    return (uint32_t)(row * 256 + 16 * (chunk ^ (row & 7)));
}
// 128B-row tile (64 bf16), chunk^(row&7) swizzle — flash Q/K/V tiles
__device__ __forceinline__ uint32_t foff(int row, int chunk) {
    return (uint32_t)(row * 128 + 16 * (chunk ^ (row & 7)));
}

// ---------------- conversion kernel (natural layout, coalesced) ----------------
__global__ void split_f32(const float* __restrict__ in,
                          __nv_bfloat16* __restrict__ hi,
                          __nv_bfloat16* __restrict__ lo, int n)
{
    int i = blockIdx.x * 256 + threadIdx.x;
    if (i < n) {
        float v = in[i];
        __nv_bfloat16 h = __float2bfloat16(v);
        hi[i] = h;
        lo[i] = __float2bfloat16(v - __bfloat162float(h));
    }
}

// ---------------- mma.sync split-bf16 GEMM (cp.async 3-stage) ----------------
// C[M,N] = A[M,K] @ W[K,N] + bias. CTA 128x128, BK=32, 8 warps, warp 64x32.
// Inner loop issues each split-term across all 4 ni before the next term:
// dependency distance on each accumulator = 4 MMAs.
#define GS_STAGE 32768
#define GS_AL    8192
#define GS_BH    16384
#define GS_BL    24576
#define GEMM_SMEM (3 * GS_STAGE)

template <bool QKV>
__global__ __launch_bounds__(256, 2)
void gemm_mma(const __nv_bfloat16* __restrict__ Ah, const __nv_bfloat16* __restrict__ Al,
              const __nv_bfloat16* __restrict__ Bh, const __nv_bfloat16* __restrict__ Bl,
              const float* __restrict__ bias, float* __restrict__ Cout,
              int Ntot, int Ktot)
{
    extern __shared__ char gs[];
    const uint32_t sb = smem_u32(gs);

    const int tid  = threadIdx.x;
    const int lane = tid & 31;
    const int wid  = tid >> 5;
    const int wm   = wid >> 2;
    const int wn   = wid & 3;
    const int m0   = blockIdx.y * 128;
    const int n0   = blockIdx.x * 128;

    float c[4][4][4];
    #pragma unroll
    for (int i = 0; i < 4; ++i)
        #pragma unroll
        for (int j = 0; j < 4; ++j)
            #pragma unroll
            for (int t = 0; t < 4; ++t) c[i][j][t] = 0.f;

    auto load_stage = [&](int stage, int k0) {
        const uint32_t s0 = sb + stage * GS_STAGE;
        #pragma unroll
        for (int it = 0; it < 2; ++it) {
            const int idx = it * 256 + tid;
            const int row = idx >> 2;
            const int cc  = idx & 3;
            const uint32_t so = tile_off(row, cc);
            const size_t ga = (size_t)(m0 + row) * Ktot + k0 + cc * 8;
            CPASYNC(s0 + so,         Ah + ga);
            CPASYNC(s0 + GS_AL + so, Al + ga);
        }
        #pragma unroll
        for (int it = 0; it < 2; ++it) {
            const int idx = it * 256 + tid;
            const int row = idx >> 4;
            const int cc  = idx & 15;
            const uint32_t so = boff(row, cc);
            const size_t gb = (size_t)(k0 + row) * Ntot + n0 + cc * 8;
            CPASYNC(s0 + GS_BH + so, Bh + gb);
            CPASYNC(s0 + GS_BL + so, Bl + gb);
        }
        CPCOMMIT();
    };

    const int nk = Ktot / 32;
    load_stage(0, 0);
    load_stage(1, 32);

    const int hilo_b = (lane >> 4) * (GS_BL - GS_BH);
    const int krow_b = lane & 15;

    int st = 0;
    for (int ki = 0; ki < nk; ++ki) {
        if (ki + 2 <= nk) { CPWAIT1(); } else { CPWAIT0(); }
        __syncthreads();
        if (ki + 2 < nk) {
            int st2 = st + 2; if (st2 >= 3) st2 -= 3;
            load_stage(st2, (ki + 2) * 32);
        }

        const uint32_t s0 = sb + st * GS_STAGE;
        #pragma unroll
        for (int ks = 0; ks < 2; ++ks) {
            uint32_t b4[4][4];
            #pragma unroll
            for (int ni = 0; ni < 4; ++ni) {
                const int chn = wn * 4 + ni;
                ldmatrix_x4_trans(b4[ni],
                    s0 + GS_BH + hilo_b + boff(ks * 16 + krow_b, chn));
            }
            #pragma unroll
            for (int mi = 0; mi < 4; ++mi) {
                uint32_t ah[4], al[4];
                const int r = wm * 64 + mi * 16 + (lane & 15);
                const uint32_t off = tile_off(r, ks * 2 + (lane >> 4));
                ldmatrix_x4(ah, s0 + off);
                ldmatrix_x4(al, s0 + GS_AL + off);
                // term-major: dep distance 4 on each accumulator
                #pragma unroll
                for (int ni = 0; ni < 4; ++ni) mma_bf16(c[mi][ni], ah, b4[ni] + 0);
                #pragma unroll
                for (int ni = 0; ni < 4; ++ni) mma_bf16(c[mi][ni], ah, b4[ni] + 2);
                #pragma unroll
                for (int ni = 0; ni < 4; ++ni) mma_bf16(c[mi][ni], al, b4[ni] + 0);
            }
        }
        if (++st >= 3) st = 0;
    }

    #pragma unroll
    for (int mi = 0; mi < 4; ++mi) {
        #pragma unroll
        for (int ni = 0; ni < 4; ++ni) {
            const int r0  = m0 + wm * 64 + mi * 16 + (lane >> 2);
            const int col = n0 + wn * 32 + ni * 8 + (lane & 3) * 2;
            const float b0 = bias[col], b1 = bias[col + 1];
            #pragma unroll
            for (int half = 0; half < 2; ++half) {
                const int r = r0 + half * 8;
                const float vx = c[mi][ni][half * 2 + 0] + b0;
                const float vy = c[mi][ni][half * 2 + 1] + b1;
                if (QKV) {
                    const int bb  = r >> 10;
                    const int iq  = r & 1023;
                    const int sel = col / DIM;
                    const int nc  = col - sel * DIM;
                    const int h   = nc >> 6;
                    const int d   = nc & 63;
                    __nv_bfloat16* dh = (sel == 0) ? g_qh : (sel == 1) ? g_kh : g_vh;
                    __nv_bfloat16* dl = (sel == 0) ? g_ql : (sel == 1) ? g_kl : g_vl;
                    const size_t idx = (((size_t)(bb * HEADS + h)) * SEQ + iq) * HD + d;
                    uint32_t hi, lo;
                    split2(vx, vy, hi, lo);
                    *(uint32_t*)(dh + idx) = hi;
                    *(uint32_t*)(dl + idx) = lo;
                } else {
                    float2 v; v.x = vx; v.y = vy;
                    *(float2*)&Cout[(size_t)r * Ntot + col] = v;
                }
            }
        }
    }
}

// ---------------- flash attention with mma.sync (cp.async 2-stage K/V) ----------------
// grid (SEQ/128, B*HEADS), 256 thr. Q resident 32KB; K/V stages 2x32KB = 96KB.
// MMA loops grouped 4-wide so each accumulator's dep distance is 4.
#define FQH 0
#define FQL 16384
#define FKV 32768
#define FKV_STRIDE 32768
#define FKL_O 8192
#define FVH_O 16384
#define FVL_O 24576
#define FLASH_SMEM (32768 + 2 * FKV_STRIDE)   // 98304

__global__ __launch_bounds__(256, 2)
void flash_mma()
{
    extern __shared__ char fs[];
    const uint32_t sb = smem_u32(fs);
    const int tid  = threadIdx.x;
    const int lane = tid & 31;
    const int wid  = tid >> 5;
    const int bh   = blockIdx.y;
    const int q0   = blockIdx.x * 128;
    const size_t base = (size_t)bh * SEQ * HD;

    auto load_kv = [&](int stage, int kb) {
        const uint32_t s0 = sb + FKV + stage * FKV_STRIDE;
        #pragma unroll
        for (int i = 0; i < 2; ++i) {
            const int idx = i * 256 + tid;
            const int row = idx >> 3, ch = idx & 7;
            const uint32_t so = foff(row, ch);
            const size_t g = base + (size_t)(kb + row) * HD + ch * 8;
            CPASYNC(s0 + so,         g_kh + g);
            CPASYNC(s0 + FKL_O + so, g_kl + g);
            CPASYNC(s0 + FVH_O + so, g_vh + g);
            CPASYNC(s0 + FVL_O + so, g_vl + g);
        }
        CPCOMMIT();
    };

    load_kv(0, 0);
    #pragma unroll
    for (int i = 0; i < 4; ++i) {
        const int idx = i * 256 + tid;
        const int row = idx >> 3, ch = idx & 7;
        const uint32_t so = foff(row, ch);
        const size_t g = base + (size_t)(q0 + row) * HD + ch * 8;
        *(uint4*)(fs + FQH + so) = *(const uint4*)(g_qh + g);
        *(uint4*)(fs + FQL + so) = *(const uint4*)(g_ql + g);
    }

    float O[8][4];
    #pragma unroll
    for (int i = 0; i < 8; ++i)
        #pragma unroll
        for (int t = 0; t < 4; ++t) O[i][t] = 0.f;
    float m0 = -1e30f, m1 = -1e30f, l0 = 0.f, l1 = 0.f;

    const int hilo_k = (lane >> 4) * FKL_O;
    const int hilo_v = (lane >> 4) * (FVL_O - FVH_O);

    const int nkb = SEQ / 64;
    for (int kbi = 0; kbi < nkb; ++kbi) {
        CPWAIT0();
        __syncthreads();
        if (kbi + 1 < nkb) load_kv((kbi + 1) & 1, (kbi + 1) * 64);

        const uint32_t s0 = sb + FKV + (kbi & 1) * FKV_STRIDE;

        // S = Q K^T
        float c[8][4];
        #pragma unroll
        for (int i = 0; i < 8; ++i)
            #pragma unroll
            for (int t = 0; t < 4; ++t) c[i][t] = 0.f;

        #pragma unroll
        for (int ks = 0; ks < 4; ++ks) {
            uint32_t qh[4], ql[4];
            {
                const int r  = wid * 16 + (lane & 15);
                const int ch = ks * 2 + (lane >> 4);
                ldmatrix_x4(qh, sb + FQH + foff(r, ch));
                ldmatrix_x4(ql, sb + FQL + foff(r, ch));
            }
            const int lr2 = lane & 7;
            const int lc2 = (lane >> 3) & 1;
            #pragma unroll
            for (int ng = 0; ng < 2; ++ng) {      // groups of 4 ni
                uint32_t kb4[4][4];
                #pragma unroll
                for (int j = 0; j < 4; ++j)
                    ldmatrix_x4(kb4[j],
                        s0 + hilo_k + foff((ng * 4 + j) * 8 + lr2, ks * 2 + lc2));
                #pragma unroll
                for (int j = 0; j < 4; ++j) mma_bf16(c[ng*4+j], qh, kb4[j] + 0);
                #pragma unroll
                for (int j = 0; j < 4; ++j) mma_bf16(c[ng*4+j], qh, kb4[j] + 2);
                #pragma unroll
                for (int j = 0; j < 4; ++j) mma_bf16(c[ng*4+j], ql, kb4[j] + 0);
            }
        }

        // scale + online softmax
        float rm0 = -1e30f, rm1 = -1e30f;
        #pragma unroll
        for (int ni = 0; ni < 8; ++ni) {
            #pragma unroll
            for (int t = 0; t < 4; ++t) c[ni][t] *= ATT_SCALE;
            rm0 = fmaxf(rm0, fmaxf(c[ni][0], c[ni][1]));
            rm1 = fmaxf(rm1, fmaxf(c[ni][2], c[ni][3]));
        }
        #pragma unroll
        for (int off = 1; off < 4; off <<= 1) {
            rm0 = fmaxf(rm0, __shfl_xor_sync(0xffffffffu, rm0, off));
            rm1 = fmaxf(rm1, __shfl_xor_sync(0xffffffffu, rm1, off));
        }
        const float mn0 = fmaxf(m0, rm0), mn1 = fmaxf(m1, rm1);
        const float cor0 = __expf(m0 - mn0), cor1 = __expf(m1 - mn1);
        m0 = mn0; m1 = mn1;

        float rs0 = 0.f, rs1 = 0.f;
        #pragma unroll
        for (int ni = 0; ni < 8; ++ni) {
            c[ni][0] = __expf(c[ni][0] - m0);
            c[ni][1] = __expf(c[ni][1] - m0);
            c[ni][2] = __expf(c[ni][2] - m1);
            c[ni][3] = __expf(c[ni][3] - m1);
            rs0 += c[ni][0] + c[ni][1];
            rs1 += c[ni][2] + c[ni][3];
        }
        #pragma unroll
        for (int off = 1; off < 4; off <<= 1) {
            rs0 += __shfl_xor_sync(0xffffffffu, rs0, off);
            rs1 += __shfl_xor_sync(0xffffffffu, rs1, off);
        }
        l0 = l0 * cor0 + rs0;
        l1 = l1 * cor1 + rs1;
        #pragma unroll
        for (int nd = 0; nd < 8; ++nd) {
            O[nd][0] *= cor0; O[nd][1] *= cor0;
            O[nd][2] *= cor1; O[nd][3] *= cor1;
        }

        // O += P V (term-major groups of 4 nd)
        #pragma unroll
        for (int ks2 = 0; ks2 < 4; ++ks2) {
            uint32_t ph[4], pl[4];
            split2(c[2*ks2][0],   c[2*ks2][1],   ph[0], pl[0]);
            split2(c[2*ks2][2],   c[2*ks2][3],   ph[1], pl[1]);
            split2(c[2*ks2+1][0], c[2*ks2+1][1], ph[2], pl[2]);
            split2(c[2*ks2+1][2], c[2*ks2+1][3], ph[3], pl[3]);
            const int vr = ks2 * 16 + (lane & 15);
            #pragma unroll
            for (int ng = 0; ng < 2; ++ng) {
                uint32_t vb4[4][4];
                #pragma unroll
                for (int j = 0; j < 4; ++j)
                    ldmatrix_x4_trans(vb4[j], s0 + FVH_O + hilo_v + foff(vr, ng * 4 + j));
                #pragma unroll
                for (int j = 0; j < 4; ++j) mma_bf16(O[ng*4+j], ph, vb4[j] + 0);
                #pragma unroll
                for (int j = 0; j < 4; ++j) mma_bf16(O[ng*4+j], ph, vb4[j] + 2);
                #pragma unroll
                for (int j = 0; j < 4; ++j) mma_bf16(O[ng*4+j], pl, vb4[j] + 0);
            }
        }
    }

    // epilogue
    const float inv0 = 1.f / l0, inv1 = 1.f / l1;
    const int b = bh / HEADS;
    const int h = bh - b * HEADS;
    const int r0 = q0 + wid * 16 + (lane >> 2);
    #pragma unroll
    for (int nd = 0; nd < 8; ++nd) {
        const int col = h * HD + nd * 8 + (lane & 3) * 2;
        uint32_t hi, lo;
        split2(O[nd][0] * inv0, O[nd][1] * inv0, hi, lo);
        size_t idx = ((size_t)(b * SEQ + r0)) * DIM + col;
        *(uint32_t*)(g_ah + idx) = hi;
        *(uint32_t*)(g_al + idx) = lo;
        split2(O[nd][2] * inv1, O[nd][3] * inv1, hi, lo);
        idx = ((size_t)(b * SEQ + r0 + 8)) * DIM + col;
        *(uint32_t*)(g_ah + idx) = hi;
        *(uint32_t*)(g_al + idx) = lo;
    }
}

// ---------------- launch ----------------
extern "C" void kernel_launch(void* const* d_in, const int* in_sizes, int n_in,
                              void* d_out, int out_size)
{
    const float* x     = (const float*)d_in[0];
    const float* w_qkv = (const float*)d_in[1];
    const float* b_qkv = (const float*)d_in[2];
    const float* w_out = (const float*)d_in[3];
    const float* b_out = (const float*)d_in[4];
    float* out = (float*)d_out;

    __nv_bfloat16 *xh, *xl, *wqh, *wql, *woh, *wol, *ah, *al;
    cudaGetSymbolAddress((void**)&xh,  g_xh);
    cudaGetSymbolAddress((void**)&xl,  g_xl);
    cudaGetSymbolAddress((void**)&wqh, g_wqh);
    cudaGetSymbolAddress((void**)&wql, g_wql);
    cudaGetSymbolAddress((void**)&woh, g_woh);
    cudaGetSymbolAddress((void**)&wol, g_wol);
    cudaGetSymbolAddress((void**)&ah,  g_ah);
    cudaGetSymbolAddress((void**)&al,  g_al);

    cudaFuncSetAttribute(gemm_mma<true>,  cudaFuncAttributeMaxDynamicSharedMemorySize, GEMM_SMEM);
    cudaFuncSetAttribute(gemm_mma<false>, cudaFuncAttributeMaxDynamicSharedMemorySize, GEMM_SMEM);
    cudaFuncSetAttribute(flash_mma, cudaFuncAttributeMaxDynamicSharedMemorySize, FLASH_SMEM);

    // 0) fp32 -> bf16 hi/lo splits (natural layout, coalesced)
    const int nx = M_TOT * DIM;
    split_f32<<<(nx + 255) / 256, 256>>>(x, xh, xl, nx);
    split_f32<<<(DIM * QKV_N + 255) / 256, 256>>>(w_qkv, wqh, wql, DIM * QKV_N);
    split_f32<<<(DIM * DIM + 255) / 256, 256>>>(w_out, woh, wol, DIM * DIM);

    // 1) QKV GEMM -> per-head bf16 hi/lo q/k/v
    gemm_mma<true><<<dim3(QKV_N / 128, M_TOT / 128), 256, GEMM_SMEM>>>(
        xh, xl, wqh, wql, b_qkv, nullptr, QKV_N, DIM);

    // 2) flash attention (HMMA) -> g_ah/g_al
    flash_mma<<<dim3(SEQ / 128, B_SZ * HEADS), 256, FLASH_SMEM>>>();

    // 3) out projection (HMMA) -> d_out
    gemm_mma<false><<<dim3(DIM / 128, M_TOT / 128), 256, GEMM_SMEM>>>(
        ah, al, woh, wol, b_out, out, DIM, DIM);
}

// round 9
// speedup vs baseline: 4.2838x; 1.0650x over previous
#include <cuda_runtime.h>
#include <cuda_bf16.h>
#include <cstdint>

#define DIM     640
#define HEADS   10
#define HD      64
#define B_SZ    16
#define SEQ     1024
#define M_TOT   (B_SZ * SEQ)     // 16384
#define QKV_N   (3 * DIM)        // 1920
// q pre-scale: DIM^-0.5 * log2(e), folded into q at QKV epilogue
#define QSCALE  0.0570280394796554f

// ---------------- scratch (device globals) ----------------
__device__ __nv_bfloat16 g_xh[(size_t)M_TOT * DIM];
__device__ __nv_bfloat16 g_xl[(size_t)M_TOT * DIM];
__device__ __nv_bfloat16 g_wqh[(size_t)DIM * QKV_N];   // w_qkv hi  [640][1920] natural
__device__ __nv_bfloat16 g_wql[(size_t)DIM * QKV_N];
__device__ __nv_bfloat16 g_woh[(size_t)DIM * DIM];     // w_out hi  [640][640] natural
__device__ __nv_bfloat16 g_wol[(size_t)DIM * DIM];
// per-head q/k/v, bf16 hi/lo: [B*HEADS][SEQ][64]  (q pre-scaled by QSCALE)
__device__ __nv_bfloat16 g_qh[(size_t)B_SZ * HEADS * SEQ * HD];
__device__ __nv_bfloat16 g_ql[(size_t)B_SZ * HEADS * SEQ * HD];
__device__ __nv_bfloat16 g_kh[(size_t)B_SZ * HEADS * SEQ * HD];
__device__ __nv_bfloat16 g_kl[(size_t)B_SZ * HEADS * SEQ * HD];
__device__ __nv_bfloat16 g_vh[(size_t)B_SZ * HEADS * SEQ * HD];
__device__ __nv_bfloat16 g_vl[(size_t)B_SZ * HEADS * SEQ * HD];
__device__ __nv_bfloat16 g_ah[(size_t)M_TOT * DIM];    // attention out hi (bf16 split)
__device__ __nv_bfloat16 g_al[(size_t)M_TOT * DIM];

// ---------------- helpers ----------------
__device__ __forceinline__ uint32_t smem_u32(const void* p) {
    uint32_t a;
    asm("{ .reg .u64 t; cvta.to.shared.u64 t, %1; cvt.u32.u64 %0, t; }"
        : "=r"(a) : "l"(p));
    return a;
}
__device__ __forceinline__ void ldmatrix_x4(uint32_t* r, uint32_t addr) {
    asm volatile("ldmatrix.sync.aligned.m8n8.x4.shared.b16 {%0,%1,%2,%3}, [%4];"
                 : "=r"(r[0]), "=r"(r[1]), "=r"(r[2]), "=r"(r[3]) : "r"(addr));
}
__device__ __forceinline__ void ldmatrix_x4_trans(uint32_t* r, uint32_t addr) {
    asm volatile("ldmatrix.sync.aligned.m8n8.x4.trans.shared.b16 {%0,%1,%2,%3}, [%4];"
                 : "=r"(r[0]), "=r"(r[1]), "=r"(r[2]), "=r"(r[3]) : "r"(addr));
}
__device__ __forceinline__ void mma_bf16(float* c, const uint32_t* a, const uint32_t* b) {
    asm volatile("mma.sync.aligned.m16n8k16.row.col.f32.bf16.bf16.f32 "
                 "{%0,%1,%2,%3}, {%4,%5,%6,%7}, {%8,%9}, {%0,%1,%2,%3};"
                 : "+f"(c[0]), "+f"(c[1]), "+f"(c[2]), "+f"(c[3])
                 : "r"(a[0]), "r"(a[1]), "r"(a[2]), "r"(a[3]), "r"(b[0]), "r"(b[1]));
}
__device__ __forceinline__ float ex2(float x) {
    float r;
    asm("ex2.approx.ftz.f32 %0, %1;" : "=f"(r) : "f"(x));
    return r;
}
__device__ __forceinline__ void split2(float x, float y, uint32_t& hi, uint32_t& lo) {
    __nv_bfloat162 h;
    h.x = __float2bfloat16(x);
    h.y = __float2bfloat16(y);
    __nv_bfloat162 l;
    l.x = __float2bfloat16(x - __bfloat162float(h.x));
    l.y = __float2bfloat16(y - __bfloat162float(h.y));
    hi = *(uint32_t*)&h;
    lo = *(uint32_t*)&l;
}

#define CPASYNC(dst, src) \
    asm volatile("cp.async.cg.shared.global [%0], [%1], 16;" \
                 :: "r"(dst), "l"(src) : "memory")
#define CPCOMMIT() asm volatile("cp.async.commit_group;" ::: "memory")
#define CPWAIT1()  asm volatile("cp.async.wait_group 1;" ::: "memory")
#define CPWAIT0()  asm volatile("cp.async.wait_group 0;" ::: "memory")

// 64B-row tile (32 bf16), chunk^((row>>1)&3) swizzle — GEMM A tiles (BK=32)
__device__ __forceinline__ uint32_t tile_off(int row, int chunk) {
    return (uint32_t)(row * 64 + 16 * (chunk ^ ((row >> 1) & 3)));
}
// 256B-row tile (128 bf16), chunk^(row&7) swizzle — GEMM B tiles [32k][128n]
__device__ __forceinline__ uint32_t boff(int row, int chunk) {
    return (uint32_t)(row * 256 + 16 * (chunk ^ (row & 7)));
}
// 128B-row tile (64 bf16), chunk^(row&7) swizzle — flash Q/K/V tiles
__device__ __forceinline__ uint32_t foff(int row, int chunk) {
    return (uint32_t)(row * 128 + 16 * (chunk ^ (row & 7)));
}

// ---------------- merged split kernel (float4-vectorized, 1 launch) ----------------
#define NX  (M_TOT * DIM)          // 10485760
#define NWQ (DIM * QKV_N)          // 1228800
#define NWO (DIM * DIM)            // 409600
#define NSPLIT4 ((NX + NWQ + NWO) / 4)

__global__ void split_all(const float* __restrict__ x,
                          const float* __restrict__ wq,
                          const float* __restrict__ wo)
{
    const int i4 = blockIdx.x * 256 + threadIdx.x;
    if (i4 >= NSPLIT4) return;
    const float* src;
    __nv_bfloat16 *hi, *lo;
    int idx = i4 * 4;
    if (idx < NX)            { src = x;  hi = g_xh;  lo = g_xl; }
    else if (idx < NX + NWQ) { idx -= NX;  src = wq; hi = g_wqh; lo = g_wql; }
    else                     { idx -= NX + NWQ; src = wo; hi = g_woh; lo = g_wol; }

    float4 v = *(const float4*)(src + idx);
    uint32_t h0, l0, h1, l1;
    split2(v.x, v.y, h0, l0);
    split2(v.z, v.w, h1, l1);
    uint2 hh; hh.x = h0; hh.y = h1;
    uint2 ll; ll.x = l0; ll.y = l1;
    *(uint2*)(hi + idx) = hh;
    *(uint2*)(lo + idx) = ll;
}

// ---------------- mma.sync split-bf16 GEMM (cp.async 3-stage) ----------------
#define GS_STAGE 32768
#define GS_AL    8192
#define GS_BH    16384
#define GS_BL    24576
#define GEMM_SMEM (3 * GS_STAGE)

template <bool QKV>
__global__ __launch_bounds__(256, 2)
void gemm_mma(const __nv_bfloat16* __restrict__ Ah, const __nv_bfloat16* __restrict__ Al,
              const __nv_bfloat16* __restrict__ Bh, const __nv_bfloat16* __restrict__ Bl,
              const float* __restrict__ bias, float* __restrict__ Cout,
              int Ntot, int Ktot)
{
    extern __shared__ char gs[];
    const uint32_t sb = smem_u32(gs);

    const int tid  = threadIdx.x;
    const int lane = tid & 31;
    const int wid  = tid >> 5;
    const int wm   = wid >> 2;
    const int wn   = wid & 3;
    const int m0   = blockIdx.y * 128;
    const int n0   = blockIdx.x * 128;

    float c[4][4][4];
    #pragma unroll
    for (int i = 0; i < 4; ++i)
        #pragma unroll
        for (int j = 0; j < 4; ++j)
            #pragma unroll
            for (int t = 0; t < 4; ++t) c[i][j][t] = 0.f;

    auto load_stage = [&](int stage, int k0) {
        const uint32_t s0 = sb + stage * GS_STAGE;
        #pragma unroll
        for (int it = 0; it < 2; ++it) {
            const int idx = it * 256 + tid;
            const int row = idx >> 2;
            const int cc  = idx & 3;
            const uint32_t so = tile_off(row, cc);
            const size_t ga = (size_t)(m0 + row) * Ktot + k0 + cc * 8;
            CPASYNC(s0 + so,         Ah + ga);
            CPASYNC(s0 + GS_AL + so, Al + ga);
        }
        #pragma unroll
        for (int it = 0; it < 2; ++it) {
            const int idx = it * 256 + tid;
            const int row = idx >> 4;
            const int cc  = idx & 15;
            const uint32_t so = boff(row, cc);
            const size_t gb = (size_t)(k0 + row) * Ntot + n0 + cc * 8;
            CPASYNC(s0 + GS_BH + so, Bh + gb);
            CPASYNC(s0 + GS_BL + so, Bl + gb);
        }
        CPCOMMIT();
    };

    const int nk = Ktot / 32;
    load_stage(0, 0);
    load_stage(1, 32);

    const int hilo_b = (lane >> 4) * (GS_BL - GS_BH);
    const int krow_b = lane & 15;

    int st = 0;
    for (int ki = 0; ki < nk; ++ki) {
        if (ki + 2 <= nk) { CPWAIT1(); } else { CPWAIT0(); }
        __syncthreads();
        if (ki + 2 < nk) {
            int st2 = st + 2; if (st2 >= 3) st2 -= 3;
            load_stage(st2, (ki + 2) * 32);
        }

        const uint32_t s0 = sb + st * GS_STAGE;
        #pragma unroll
        for (int ks = 0; ks < 2; ++ks) {
            uint32_t b4[4][4];
            #pragma unroll
            for (int ni = 0; ni < 4; ++ni) {
                const int chn = wn * 4 + ni;
                ldmatrix_x4_trans(b4[ni],
                    s0 + GS_BH + hilo_b + boff(ks * 16 + krow_b, chn));
            }
            #pragma unroll
            for (int mi = 0; mi < 4; ++mi) {
                uint32_t ah[4], al[4];
                const int r = wm * 64 + mi * 16 + (lane & 15);
                const uint32_t off = tile_off(r, ks * 2 + (lane >> 4));
                ldmatrix_x4(ah, s0 + off);
                ldmatrix_x4(al, s0 + GS_AL + off);
                #pragma unroll
                for (int ni = 0; ni < 4; ++ni) mma_bf16(c[mi][ni], ah, b4[ni] + 0);
                #pragma unroll
                for (int ni = 0; ni < 4; ++ni) mma_bf16(c[mi][ni], ah, b4[ni] + 2);
                #pragma unroll
                for (int ni = 0; ni < 4; ++ni) mma_bf16(c[mi][ni], al, b4[ni] + 0);
            }
        }
        if (++st >= 3) st = 0;
    }

    #pragma unroll
    for (int mi = 0; mi < 4; ++mi) {
        #pragma unroll
        for (int ni = 0; ni < 4; ++ni) {
            const int r0  = m0 + wm * 64 + mi * 16 + (lane >> 2);
            const int col = n0 + wn * 32 + ni * 8 + (lane & 3) * 2;
            const float b0 = bias[col], b1 = bias[col + 1];
            #pragma unroll
            for (int half = 0; half < 2; ++half) {
                const int r = r0 + half * 8;
                float vx = c[mi][ni][half * 2 + 0] + b0;
                float vy = c[mi][ni][half * 2 + 1] + b1;
                if (QKV) {
                    const int bb  = r >> 10;
                    const int iq  = r & 1023;
                    const int sel = col / DIM;
                    const int nc  = col - sel * DIM;
                    const int h   = nc >> 6;
                    const int d   = nc & 63;
                    if (sel == 0) { vx *= QSCALE; vy *= QSCALE; }  // fold softmax scale+log2e into q
                    __nv_bfloat16* dh = (sel == 0) ? g_qh : (sel == 1) ? g_kh : g_vh;
                    __nv_bfloat16* dl = (sel == 0) ? g_ql : (sel == 1) ? g_kl : g_vl;
                    const size_t idx = (((size_t)(bb * HEADS + h)) * SEQ + iq) * HD + d;
                    uint32_t hi, lo;
                    split2(vx, vy, hi, lo);
                    *(uint32_t*)(dh + idx) = hi;
                    *(uint32_t*)(dl + idx) = lo;
                } else {
                    float2 v; v.x = vx; v.y = vy;
                    *(float2*)&Cout[(size_t)r * Ntot + col] = v;
                }
            }
        }
    }
}

// ---------------- flash attention with mma.sync (cp.async 2-stage K/V) ----------------
// Softmax runs in log2 domain (q pre-scaled); ex2.approx; skip-rescale when max stable.
#define FQH 0
#define FQL 16384
#define FKV 32768
#define FKV_STRIDE 32768
#define FKL_O 8192
#define FVH_O 16384
#define FVL_O 24576
#define FLASH_SMEM (32768 + 2 * FKV_STRIDE)   // 98304

__global__ __launch_bounds__(256, 2)
void flash_mma()
{
    extern __shared__ char fs[];
    const uint32_t sb = smem_u32(fs);
    const int tid  = threadIdx.x;
    const int lane = tid & 31;
    const int wid  = tid >> 5;
    const int bh   = blockIdx.y;
    const int q0   = blockIdx.x * 128;
    const size_t base = (size_t)bh * SEQ * HD;

    auto load_kv = [&](int stage, int kb) {
        const uint32_t s0 = sb + FKV + stage * FKV_STRIDE;
        #pragma unroll
        for (int i = 0; i < 2; ++i) {
            const int idx = i * 256 + tid;
            const int row = idx >> 3, ch = idx & 7;
            const uint32_t so = foff(row, ch);
            const size_t g = base + (size_t)(kb + row) * HD + ch * 8;
            CPASYNC(s0 + so,         g_kh + g);
            CPASYNC(s0 + FKL_O + so, g_kl + g);
            CPASYNC(s0 + FVH_O + so, g_vh + g);
            CPASYNC(s0 + FVL_O + so, g_vl + g);
        }
        CPCOMMIT();
    };

    load_kv(0, 0);
    #pragma unroll
    for (int i = 0; i < 4; ++i) {
        const int idx = i * 256 + tid;
        const int row = idx >> 3, ch = idx & 7;
        const uint32_t so = foff(row, ch);
        const size_t g = base + (size_t)(q0 + row) * HD + ch * 8;
        *(uint4*)(fs + FQH + so) = *(const uint4*)(g_qh + g);
        *(uint4*)(fs + FQL + so) = *(const uint4*)(g_ql + g);
    }

    float O[8][4];
    #pragma unroll
    for (int i = 0; i < 8; ++i)
        #pragma unroll
        for (int t = 0; t < 4; ++t) O[i][t] = 0.f;
    float m0 = -1e30f, m1 = -1e30f, l0 = 0.f, l1 = 0.f;

    const int hilo_k = (lane >> 4) * FKL_O;
    const int hilo_v = (lane >> 4) * (FVL_O - FVH_O);

    const int nkb = SEQ / 64;
    for (int kbi = 0; kbi < nkb; ++kbi) {
        CPWAIT0();
        __syncthreads();
        if (kbi + 1 < nkb) load_kv((kbi + 1) & 1, (kbi + 1) * 64);

        const uint32_t s0 = sb + FKV + (kbi & 1) * FKV_STRIDE;

        // S2 = (q*QSCALE) K^T  — already in log2 domain
        float c[8][4];
        #pragma unroll
        for (int i = 0; i < 8; ++i)
            #pragma unroll
            for (int t = 0; t < 4; ++t) c[i][t] = 0.f;

        #pragma unroll
        for (int ks = 0; ks < 4; ++ks) {
            uint32_t qh[4], ql[4];
            {
                const int r  = wid * 16 + (lane & 15);
                const int ch = ks * 2 + (lane >> 4);
                ldmatrix_x4(qh, sb + FQH + foff(r, ch));
                ldmatrix_x4(ql, sb + FQL + foff(r, ch));
            }
            const int lr2 = lane & 7;
            const int lc2 = (lane >> 3) & 1;
            #pragma unroll
            for (int ng = 0; ng < 2; ++ng) {
                uint32_t kb4[4][4];
                #pragma unroll
                for (int j = 0; j < 4; ++j)
                    ldmatrix_x4(kb4[j],
                        s0 + hilo_k + foff((ng * 4 + j) * 8 + lr2, ks * 2 + lc2));
                #pragma unroll
                for (int j = 0; j < 4; ++j) mma_bf16(c[ng*4+j], qh, kb4[j] + 0);
                #pragma unroll
                for (int j = 0; j < 4; ++j) mma_bf16(c[ng*4+j], qh, kb4[j] + 2);
                #pragma unroll
                for (int j = 0; j < 4; ++j) mma_bf16(c[ng*4+j], ql, kb4[j] + 0);
            }
        }

        // online softmax (log2 domain)
        float rm0 = -1e30f, rm1 = -1e30f;
        #pragma unroll
        for (int ni = 0; ni < 8; ++ni) {
            rm0 = fmaxf(rm0, fmaxf(c[ni][0], c[ni][1]));
            rm1 = fmaxf(rm1, fmaxf(c[ni][2], c[ni][3]));
        }
        #pragma unroll
        for (int off = 1; off < 4; off <<= 1) {
            rm0 = fmaxf(rm0, __shfl_xor_sync(0xffffffffu, rm0, off));
            rm1 = fmaxf(rm1, __shfl_xor_sync(0xffffffffu, rm1, off));
        }
        const float mn0 = fmaxf(m0, rm0), mn1 = fmaxf(m1, rm1);
        // skip rescale if no row in the warp saw a new max
        if (!__all_sync(0xffffffffu, (mn0 == m0) && (mn1 == m1))) {
            const float cor0 = ex2(m0 - mn0), cor1 = ex2(m1 - mn1);
            l0 *= cor0; l1 *= cor1;
            #pragma unroll
            for (int nd = 0; nd < 8; ++nd) {
                O[nd][0] *= cor0; O[nd][1] *= cor0;
                O[nd][2] *= cor1; O[nd][3] *= cor1;
            }
            m0 = mn0; m1 = mn1;
        }

        float rs0 = 0.f, rs1 = 0.f;
        #pragma unroll
        for (int ni = 0; ni < 8; ++ni) {
            c[ni][0] = ex2(c[ni][0] - m0);
            c[ni][1] = ex2(c[ni][1] - m0);
            c[ni][2] = ex2(c[ni][2] - m1);
            c[ni][3] = ex2(c[ni][3] - m1);
            rs0 += c[ni][0] + c[ni][1];
            rs1 += c[ni][2] + c[ni][3];
        }
        #pragma unroll
        for (int off = 1; off < 4; off <<= 1) {
            rs0 += __shfl_xor_sync(0xffffffffu, rs0, off);
            rs1 += __shfl_xor_sync(0xffffffffu, rs1, off);
        }
        l0 += rs0;
        l1 += rs1;

        // O += P V (term-major groups of 4 nd)
        #pragma unroll
        for (int ks2 = 0; ks2 < 4; ++ks2) {
            uint32_t ph[4], pl[4];
            split2(c[2*ks2][0],   c[2*ks2][1],   ph[0], pl[0]);
            split2(c[2*ks2][2],   c[2*ks2][3],   ph[1], pl[1]);
            split2(c[2*ks2+1][0], c[2*ks2+1][1], ph[2], pl[2]);
            split2(c[2*ks2+1][2], c[2*ks2+1][3], ph[3], pl[3]);
            const int vr = ks2 * 16 + (lane & 15);
            #pragma unroll
            for (int ng = 0; ng < 2; ++ng) {
                uint32_t vb4[4][4];
                #pragma unroll
                for (int j = 0; j < 4; ++j)
                    ldmatrix_x4_trans(vb4[j], s0 + FVH_O + hilo_v + foff(vr, ng * 4 + j));
                #pragma unroll
                for (int j = 0; j < 4; ++j) mma_bf16(O[ng*4+j], ph, vb4[j] + 0);
                #pragma unroll
                for (int j = 0; j < 4; ++j) mma_bf16(O[ng*4+j], ph, vb4[j] + 2);
                #pragma unroll
                for (int j = 0; j < 4; ++j) mma_bf16(O[ng*4+j], pl, vb4[j] + 0);
            }
        }
    }

    // epilogue
    const float inv0 = 1.f / l0, inv1 = 1.f / l1;
    const int b = bh / HEADS;
    const int h = bh - b * HEADS;
    const int r0 = q0 + wid * 16 + (lane >> 2);
    #pragma unroll
    for (int nd = 0; nd < 8; ++nd) {
        const int col = h * HD + nd * 8 + (lane & 3) * 2;
        uint32_t hi, lo;
        split2(O[nd][0] * inv0, O[nd][1] * inv0, hi, lo);
        size_t idx = ((size_t)(b * SEQ + r0)) * DIM + col;
        *(uint32_t*)(g_ah + idx) = hi;
        *(uint32_t*)(g_al + idx) = lo;
        split2(O[nd][2] * inv1, O[nd][3] * inv1, hi, lo);
        idx = ((size_t)(b * SEQ + r0 + 8)) * DIM + col;
        *(uint32_t*)(g_ah + idx) = hi;
        *(uint32_t*)(g_al + idx) = lo;
    }
}

// ---------------- launch ----------------
extern "C" void kernel_launch(void* const* d_in, const int* in_sizes, int n_in,
                              void* d_out, int out_size)
{
    const float* x     = (const float*)d_in[0];
    const float* w_qkv = (const float*)d_in[1];
    const float* b_qkv = (const float*)d_in[2];
    const float* w_out = (const float*)d_in[3];
    const float* b_out = (const float*)d_in[4];
    float* out = (float*)d_out;

    __nv_bfloat16 *xh, *xl, *wqh, *wql, *woh, *wol, *ah, *al;
    cudaGetSymbolAddress((void**)&xh,  g_xh);
    cudaGetSymbolAddress((void**)&xl,  g_xl);
    cudaGetSymbolAddress((void**)&wqh, g_wqh);
    cudaGetSymbolAddress((void**)&wql, g_wql);
    cudaGetSymbolAddress((void**)&woh, g_woh);
    cudaGetSymbolAddress((void**)&wol, g_wol);
    cudaGetSymbolAddress((void**)&ah,  g_ah);
    cudaGetSymbolAddress((void**)&al,  g_al);

    cudaFuncSetAttribute(gemm_mma<true>,  cudaFuncAttributeMaxDynamicSharedMemorySize, GEMM_SMEM);
    cudaFuncSetAttribute(gemm_mma<false>, cudaFuncAttributeMaxDynamicSharedMemorySize, GEMM_SMEM);
    cudaFuncSetAttribute(flash_mma, cudaFuncAttributeMaxDynamicSharedMemorySize, FLASH_SMEM);

    // 0) all fp32 -> bf16 hi/lo splits in one vectorized launch
    split_all<<<(NSPLIT4 + 255) / 256, 256>>>(x, w_qkv, w_out);

    // 1) QKV GEMM -> per-head bf16 hi/lo q/k/v (q pre-scaled)
    gemm_mma<true><<<dim3(QKV_N / 128, M_TOT / 128), 256, GEMM_SMEM>>>(
        xh, xl, wqh, wql, b_qkv, nullptr, QKV_N, DIM);

    // 2) flash attention (HMMA, log2-domain softmax) -> g_ah/g_al
    flash_mma<<<dim3(SEQ / 128, B_SZ * HEADS), 256, FLASH_SMEM>>>();

    // 3) out projection (HMMA) -> d_out
    gemm_mma<false><<<dim3(DIM / 128, M_TOT / 128), 256, GEMM_SMEM>>>(
        ah, al, woh, wol, b_out, out, DIM, DIM);
}

// round 10
// speedup vs baseline: 4.3179x; 1.0080x over previous
#include <cuda_runtime.h>
#include <cuda_bf16.h>
#include <cstdint>

#define DIM     640
#define HEADS   10
#define HD      64
#define B_SZ    16
#define SEQ     1024
#define M_TOT   (B_SZ * SEQ)     // 16384
#define QKV_N   (3 * DIM)        // 1920
// q pre-scale: DIM^-0.5 * log2(e), folded into q at QKV epilogue
#define QSCALE  0.0570280394796554f

// ---------------- scratch (device globals) ----------------
__device__ __nv_bfloat16 g_xh[(size_t)M_TOT * DIM];
__device__ __nv_bfloat16 g_xl[(size_t)M_TOT * DIM];
__device__ __nv_bfloat16 g_wqh[(size_t)DIM * QKV_N];   // w_qkv hi  [640][1920] natural
__device__ __nv_bfloat16 g_wql[(size_t)DIM * QKV_N];
__device__ __nv_bfloat16 g_woh[(size_t)DIM * DIM];     // w_out hi  [640][640] natural
__device__ __nv_bfloat16 g_wol[(size_t)DIM * DIM];
// per-head q/k/v, bf16 hi/lo: [B*HEADS][SEQ][64]  (q pre-scaled by QSCALE)
__device__ __nv_bfloat16 g_qh[(size_t)B_SZ * HEADS * SEQ * HD];
__device__ __nv_bfloat16 g_ql[(size_t)B_SZ * HEADS * SEQ * HD];
__device__ __nv_bfloat16 g_kh[(size_t)B_SZ * HEADS * SEQ * HD];
__device__ __nv_bfloat16 g_kl[(size_t)B_SZ * HEADS * SEQ * HD];
__device__ __nv_bfloat16 g_vh[(size_t)B_SZ * HEADS * SEQ * HD];
__device__ __nv_bfloat16 g_vl[(size_t)B_SZ * HEADS * SEQ * HD];
__device__ __nv_bfloat16 g_ah[(size_t)M_TOT * DIM];    // attention out hi (bf16 split)
__device__ __nv_bfloat16 g_al[(size_t)M_TOT * DIM];

// ---------------- helpers ----------------
__device__ __forceinline__ uint32_t smem_u32(const void* p) {
    uint32_t a;
    asm("{ .reg .u64 t; cvta.to.shared.u64 t, %1; cvt.u32.u64 %0, t; }"
        : "=r"(a) : "l"(p));
    return a;
}
__device__ __forceinline__ void ldmatrix_x4(uint32_t* r, uint32_t addr) {
    asm volatile("ldmatrix.sync.aligned.m8n8.x4.shared.b16 {%0,%1,%2,%3}, [%4];"
                 : "=r"(r[0]), "=r"(r[1]), "=r"(r[2]), "=r"(r[3]) : "r"(addr));
}
__device__ __forceinline__ void ldmatrix_x4_trans(uint32_t* r, uint32_t addr) {
    asm volatile("ldmatrix.sync.aligned.m8n8.x4.trans.shared.b16 {%0,%1,%2,%3}, [%4];"
                 : "=r"(r[0]), "=r"(r[1]), "=r"(r[2]), "=r"(r[3]) : "r"(addr));
}
__device__ __forceinline__ void mma_bf16(float* c, const uint32_t* a, const uint32_t* b) {
    asm volatile("mma.sync.aligned.m16n8k16.row.col.f32.bf16.bf16.f32 "
                 "{%0,%1,%2,%3}, {%4,%5,%6,%7}, {%8,%9}, {%0,%1,%2,%3};"
                 : "+f"(c[0]), "+f"(c[1]), "+f"(c[2]), "+f"(c[3])
                 : "r"(a[0]), "r"(a[1]), "r"(a[2]), "r"(a[3]), "r"(b[0]), "r"(b[1]));
}
__device__ __forceinline__ float ex2(float x) {
    float r;
    asm("ex2.approx.ftz.f32 %0, %1;" : "=f"(r) : "f"(x));
    return r;
}
__device__ __forceinline__ void split2(float x, float y, uint32_t& hi, uint32_t& lo) {
    __nv_bfloat162 h;
    h.x = __float2bfloat16(x);
    h.y = __float2bfloat16(y);
    __nv_bfloat162 l;
    l.x = __float2bfloat16(x - __bfloat162float(h.x));
    l.y = __float2bfloat16(y - __bfloat162float(h.y));
    hi = *(uint32_t*)&h;
    lo = *(uint32_t*)&l;
}

#define CPASYNC(dst, src) \
    asm volatile("cp.async.cg.shared.global [%0], [%1], 16;" \
                 :: "r"(dst), "l"(src) : "memory")
#define CPCOMMIT() asm volatile("cp.async.commit_group;" ::: "memory")
#define CPWAIT1()  asm volatile("cp.async.wait_group 1;" ::: "memory")
#define CPWAIT0()  asm volatile("cp.async.wait_group 0;" ::: "memory")

// 64B-row tile (32 bf16), chunk^((row>>1)&3) swizzle — GEMM A tiles (BK=32)
__device__ __forceinline__ uint32_t tile_off(int row, int chunk) {
    return (uint32_t)(row * 64 + 16 * (chunk ^ ((row >> 1) & 3)));
}
// 256B-row tile (128 bf16), chunk^(row&7) swizzle — GEMM B tiles [32k][128n]
__device__ __forceinline__ uint32_t boff(int row, int chunk) {
    return (uint32_t)(row * 256 + 16 * (chunk ^ (row & 7)));
}
// 128B-row tile (64 bf16), chunk^(row&7) swizzle — flash Q/K/V tiles
__device__ __forceinline__ uint32_t foff(int row, int chunk) {
    return (uint32_t)(row * 128 + 16 * (chunk ^ (row & 7)));
}

// ---------------- merged split kernel (float4-vectorized, 1 launch) ----------------
#define NX  (M_TOT * DIM)          // 10485760
#define NWQ (DIM * QKV_N)          // 1228800
#define NWO (DIM * DIM)            // 409600
#define NSPLIT4 ((NX + NWQ + NWO) / 4)

__global__ void split_all(const float* __restrict__ x,
                          const float* __restrict__ wq,
                          const float* __restrict__ wo)
{
    const int i4 = blockIdx.x * 256 + threadIdx.x;
    if (i4 >= NSPLIT4) return;
    const float* src;
    __nv_bfloat16 *hi, *lo;
    int idx = i4 * 4;
    if (idx < NX)            { src = x;  hi = g_xh;  lo = g_xl; }
    else if (idx < NX + NWQ) { idx -= NX;  src = wq; hi = g_wqh; lo = g_wql; }
    else                     { idx -= NX + NWQ; src = wo; hi = g_woh; lo = g_wol; }

    float4 v = *(const float4*)(src + idx);
    uint32_t h0, l0, h1, l1;
    split2(v.x, v.y, h0, l0);
    split2(v.z, v.w, h1, l1);
    uint2 hh; hh.x = h0; hh.y = h1;
    uint2 ll; ll.x = l0; ll.y = l1;
    *(uint2*)(hi + idx) = hh;
    *(uint2*)(lo + idx) = ll;
}

// ---------------- mma.sync split-bf16 GEMM (cp.async 3-stage) ----------------
// C[M,N] = A[M,K] @ W[K,N] + bias. CTA tile MT x 128, BK=32, 8 warps.
// MT=128: warp 64x32 (mi=4). MT=64: warp 32x32 (mi=2) — finer grid for tails.
#define GS_STAGE 32768
#define GS_AL    8192
#define GS_BH    16384
#define GS_BL    24576
#define GEMM_SMEM (3 * GS_STAGE)

template <bool QKV, int MT>
__global__ __launch_bounds__(256, 2)
void gemm_mma(const __nv_bfloat16* __restrict__ Ah, const __nv_bfloat16* __restrict__ Al,
              const __nv_bfloat16* __restrict__ Bh, const __nv_bfloat16* __restrict__ Bl,
              const float* __restrict__ bias, float* __restrict__ Cout,
              int Ntot, int Ktot)
{
    extern __shared__ char gs[];
    const uint32_t sb = smem_u32(gs);

    constexpr int MI = MT / 32;          // m-frags per warp
    const int tid  = threadIdx.x;
    const int lane = tid & 31;
    const int wid  = tid >> 5;
    const int wm   = wid >> 2;
    const int wn   = wid & 3;
    const int m0   = blockIdx.y * MT;
    const int n0   = blockIdx.x * 128;

    float c[MI][4][4];
    #pragma unroll
    for (int i = 0; i < MI; ++i)
        #pragma unroll
        for (int j = 0; j < 4; ++j)
            #pragma unroll
            for (int t = 0; t < 4; ++t) c[i][j][t] = 0.f;

    auto load_stage = [&](int stage, int k0) {
        const uint32_t s0 = sb + stage * GS_STAGE;
        #pragma unroll
        for (int it = 0; it < MT / 64; ++it) {
            const int idx = it * 256 + tid;
            const int row = idx >> 2;
            const int cc  = idx & 3;
            const uint32_t so = tile_off(row, cc);
            const size_t ga = (size_t)(m0 + row) * Ktot + k0 + cc * 8;
            CPASYNC(s0 + so,         Ah + ga);
            CPASYNC(s0 + GS_AL + so, Al + ga);
        }
        #pragma unroll
        for (int it = 0; it < 2; ++it) {
            const int idx = it * 256 + tid;
            const int row = idx >> 4;
            const int cc  = idx & 15;
            const uint32_t so = boff(row, cc);
            const size_t gb = (size_t)(k0 + row) * Ntot + n0 + cc * 8;
            CPASYNC(s0 + GS_BH + so, Bh + gb);
            CPASYNC(s0 + GS_BL + so, Bl + gb);
        }
        CPCOMMIT();
    };

    const int nk = Ktot / 32;
    load_stage(0, 0);
    load_stage(1, 32);

    const int hilo_b = (lane >> 4) * (GS_BL - GS_BH);
    const int krow_b = lane & 15;

    int st = 0;
    for (int ki = 0; ki < nk; ++ki) {
        if (ki + 2 <= nk) { CPWAIT1(); } else { CPWAIT0(); }
        __syncthreads();
        if (ki + 2 < nk) {
            int st2 = st + 2; if (st2 >= 3) st2 -= 3;
            load_stage(st2, (ki + 2) * 32);
        }

        const uint32_t s0 = sb + st * GS_STAGE;
        #pragma unroll
        for (int ks = 0; ks < 2; ++ks) {
            uint32_t b4[4][4];
            #pragma unroll
            for (int ni = 0; ni < 4; ++ni) {
                const int chn = wn * 4 + ni;
                ldmatrix_x4_trans(b4[ni],
                    s0 + GS_BH + hilo_b + boff(ks * 16 + krow_b, chn));
            }
            #pragma unroll
            for (int mi = 0; mi < MI; ++mi) {
                uint32_t ah[4], al[4];
                const int r = wm * (MT / 2) + mi * 16 + (lane & 15);
                const uint32_t off = tile_off(r, ks * 2 + (lane >> 4));
                ldmatrix_x4(ah, s0 + off);
                ldmatrix_x4(al, s0 + GS_AL + off);
                #pragma unroll
                for (int ni = 0; ni < 4; ++ni) mma_bf16(c[mi][ni], ah, b4[ni] + 0);
                #pragma unroll
                for (int ni = 0; ni < 4; ++ni) mma_bf16(c[mi][ni], ah, b4[ni] + 2);
                #pragma unroll
                for (int ni = 0; ni < 4; ++ni) mma_bf16(c[mi][ni], al, b4[ni] + 0);
            }
        }
        if (++st >= 3) st = 0;
    }

    #pragma unroll
    for (int mi = 0; mi < MI; ++mi) {
        #pragma unroll
        for (int ni = 0; ni < 4; ++ni) {
            const int r0  = m0 + wm * (MT / 2) + mi * 16 + (lane >> 2);
            const int col = n0 + wn * 32 + ni * 8 + (lane & 3) * 2;
            const float b0 = bias[col], b1 = bias[col + 1];
            #pragma unroll
            for (int half = 0; half < 2; ++half) {
                const int r = r0 + half * 8;
                float vx = c[mi][ni][half * 2 + 0] + b0;
                float vy = c[mi][ni][half * 2 + 1] + b1;
                if (QKV) {
                    const int bb  = r >> 10;
                    const int iq  = r & 1023;
                    const int sel = col / DIM;
                    const int nc  = col - sel * DIM;
                    const int h   = nc >> 6;
                    const int d   = nc & 63;
                    if (sel == 0) { vx *= QSCALE; vy *= QSCALE; }
                    __nv_bfloat16* dh = (sel == 0) ? g_qh : (sel == 1) ? g_kh : g_vh;
                    __nv_bfloat16* dl = (sel == 0) ? g_ql : (sel == 1) ? g_kl : g_vl;
                    const size_t idx = (((size_t)(bb * HEADS + h)) * SEQ + iq) * HD + d;
                    uint32_t hi, lo;
                    split2(vx, vy, hi, lo);
                    *(uint32_t*)(dh + idx) = hi;
                    *(uint32_t*)(dl + idx) = lo;
                } else {
                    float2 v; v.x = vx; v.y = vy;
                    *(float2*)&Cout[(size_t)r * Ntot + col] = v;
                }
            }
        }
    }
}

// ---------------- flash attention with mma.sync (cp.async 2-stage K/V) ----------------
#define FQH 0
#define FQL 16384
#define FKV 32768
#define FKV_STRIDE 32768
#define FKL_O 8192
#define FVH_O 16384
#define FVL_O 24576
#define FLASH_SMEM (32768 + 2 * FKV_STRIDE)   // 98304

__global__ __launch_bounds__(256, 2)
void flash_mma()
{
    extern __shared__ char fs[];
    const uint32_t sb = smem_u32(fs);
    const int tid  = threadIdx.x;
    const int lane = tid & 31;
    const int wid  = tid >> 5;
    const int bh   = blockIdx.y;
    const int q0   = blockIdx.x * 128;
    const size_t base = (size_t)bh * SEQ * HD;

    auto load_kv = [&](int stage, int kb) {
        const uint32_t s0 = sb + FKV + stage * FKV_STRIDE;
        #pragma unroll
        for (int i = 0; i < 2; ++i) {
            const int idx = i * 256 + tid;
            const int row = idx >> 3, ch = idx & 7;
            const uint32_t so = foff(row, ch);
            const size_t g = base + (size_t)(kb + row) * HD + ch * 8;
            CPASYNC(s0 + so,         g_kh + g);
            CPASYNC(s0 + FKL_O + so, g_kl + g);
            CPASYNC(s0 + FVH_O + so, g_vh + g);
            CPASYNC(s0 + FVL_O + so, g_vl + g);
        }
        CPCOMMIT();
    };

    load_kv(0, 0);
    #pragma unroll
    for (int i = 0; i < 4; ++i) {
        const int idx = i * 256 + tid;
        const int row = idx >> 3, ch = idx & 7;
        const uint32_t so = foff(row, ch);
        const size_t g = base + (size_t)(q0 + row) * HD + ch * 8;
        *(uint4*)(fs + FQH + so) = *(const uint4*)(g_qh + g);
        *(uint4*)(fs + FQL + so) = *(const uint4*)(g_ql + g);
    }

    float O[8][4];
    #pragma unroll
    for (int i = 0; i < 8; ++i)
        #pragma unroll
        for (int t = 0; t < 4; ++t) O[i][t] = 0.f;
    float m0 = -1e30f, m1 = -1e30f, l0 = 0.f, l1 = 0.f;

    const int hilo_k = (lane >> 4) * FKL_O;
    const int hilo_v = (lane >> 4) * (FVL_O - FVH_O);

    const int nkb = SEQ / 64;
    for (int kbi = 0; kbi < nkb; ++kbi) {
        CPWAIT0();
        __syncthreads();
        if (kbi + 1 < nkb) load_kv((kbi + 1) & 1, (kbi + 1) * 64);

        const uint32_t s0 = sb + FKV + (kbi & 1) * FKV_STRIDE;

        float c[8][4];
        #pragma unroll
        for (int i = 0; i < 8; ++i)
            #pragma unroll
            for (int t = 0; t < 4; ++t) c[i][t] = 0.f;

        #pragma unroll
        for (int ks = 0; ks < 4; ++ks) {
            uint32_t qh[4], ql[4];
            {
                const int r  = wid * 16 + (lane & 15);
                const int ch = ks * 2 + (lane >> 4);
                ldmatrix_x4(qh, sb + FQH + foff(r, ch));
                ldmatrix_x4(ql, sb + FQL + foff(r, ch));
            }
            const int lr2 = lane & 7;
            const int lc2 = (lane >> 3) & 1;
            #pragma unroll
            for (int ng = 0; ng < 2; ++ng) {
                uint32_t kb4[4][4];
                #pragma unroll
                for (int j = 0; j < 4; ++j)
                    ldmatrix_x4(kb4[j],
                        s0 + hilo_k + foff((ng * 4 + j) * 8 + lr2, ks * 2 + lc2));
                #pragma unroll
                for (int j = 0; j < 4; ++j) mma_bf16(c[ng*4+j], qh, kb4[j] + 0);
                #pragma unroll
                for (int j = 0; j < 4; ++j) mma_bf16(c[ng*4+j], qh, kb4[j] + 2);
                #pragma unroll
                for (int j = 0; j < 4; ++j) mma_bf16(c[ng*4+j], ql, kb4[j] + 0);
            }
        }

        // online softmax (log2 domain)
        float rm0 = -1e30f, rm1 = -1e30f;
        #pragma unroll
        for (int ni = 0; ni < 8; ++ni) {
            rm0 = fmaxf(rm0, fmaxf(c[ni][0], c[ni][1]));
            rm1 = fmaxf(rm1, fmaxf(c[ni][2], c[ni][3]));
        }
        #pragma unroll
        for (int off = 1; off < 4; off <<= 1) {
            rm0 = fmaxf(rm0, __shfl_xor_sync(0xffffffffu, rm0, off));
            rm1 = fmaxf(rm1, __shfl_xor_sync(0xffffffffu, rm1, off));
        }
        const float mn0 = fmaxf(m0, rm0), mn1 = fmaxf(m1, rm1);
        if (!__all_sync(0xffffffffu, (mn0 == m0) && (mn1 == m1))) {
            const float cor0 = ex2(m0 - mn0), cor1 = ex2(m1 - mn1);
            l0 *= cor0; l1 *= cor1;
            #pragma unroll
            for (int nd = 0; nd < 8; ++nd) {
                O[nd][0] *= cor0; O[nd][1] *= cor0;
                O[nd][2] *= cor1; O[nd][3] *= cor1;
            }
            m0 = mn0; m1 = mn1;
        }

        float rs0 = 0.f, rs1 = 0.f;
        #pragma unroll
        for (int ni = 0; ni < 8; ++ni) {
            c[ni][0] = ex2(c[ni][0] - m0);
            c[ni][1] = ex2(c[ni][1] - m0);
            c[ni][2] = ex2(c[ni][2] - m1);
            c[ni][3] = ex2(c[ni][3] - m1);
            rs0 += c[ni][0] + c[ni][1];
            rs1 += c[ni][2] + c[ni][3];
        }
        #pragma unroll
        for (int off = 1; off < 4; off <<= 1) {
            rs0 += __shfl_xor_sync(0xffffffffu, rs0, off);
            rs1 += __shfl_xor_sync(0xffffffffu, rs1, off);
        }
        l0 += rs0;
        l1 += rs1;

        // O += P V
        #pragma unroll
        for (int ks2 = 0; ks2 < 4; ++ks2) {
            uint32_t ph[4], pl[4];
            split2(c[2*ks2][0],   c[2*ks2][1],   ph[0], pl[0]);
            split2(c[2*ks2][2],   c[2*ks2][3],   ph[1], pl[1]);
            split2(c[2*ks2+1][0], c[2*ks2+1][1], ph[2], pl[2]);
            split2(c[2*ks2+1][2], c[2*ks2+1][3], ph[3], pl[3]);
            const int vr = ks2 * 16 + (lane & 15);
            #pragma unroll
            for (int ng = 0; ng < 2; ++ng) {
                uint32_t vb4[4][4];
                #pragma unroll
                for (int j = 0; j < 4; ++j)
                    ldmatrix_x4_trans(vb4[j], s0 + FVH_O + hilo_v + foff(vr, ng * 4 + j));
                #pragma unroll
                for (int j = 0; j < 4; ++j) mma_bf16(O[ng*4+j], ph, vb4[j] + 0);
                #pragma unroll
                for (int j = 0; j < 4; ++j) mma_bf16(O[ng*4+j], ph, vb4[j] + 2);
                #pragma unroll
                for (int j = 0; j < 4; ++j) mma_bf16(O[ng*4+j], pl, vb4[j] + 0);
            }
        }
    }

    // epilogue
    const float inv0 = 1.f / l0, inv1 = 1.f / l1;
    const int b = bh / HEADS;
    const int h = bh - b * HEADS;
    const int r0 = q0 + wid * 16 + (lane >> 2);
    #pragma unroll
    for (int nd = 0; nd < 8; ++nd) {
        const int col = h * HD + nd * 8 + (lane & 3) * 2;
        uint32_t hi, lo;
        split2(O[nd][0] * inv0, O[nd][1] * inv0, hi, lo);
        size_t idx = ((size_t)(b * SEQ + r0)) * DIM + col;
        *(uint32_t*)(g_ah + idx) = hi;
        *(uint32_t*)(g_al + idx) = lo;
        split2(O[nd][2] * inv1, O[nd][3] * inv1, hi, lo);
        idx = ((size_t)(b * SEQ + r0 + 8)) * DIM + col;
        *(uint32_t*)(g_ah + idx) = hi;
        *(uint32_t*)(g_al + idx) = lo;
    }
}

// ---------------- launch ----------------
extern "C" void kernel_launch(void* const* d_in, const int* in_sizes, int n_in,
                              void* d_out, int out_size)
{
    const float* x     = (const float*)d_in[0];
    const float* w_qkv = (const float*)d_in[1];
    const float* b_qkv = (const float*)d_in[2];
    const float* w_out = (const float*)d_in[3];
    const float* b_out = (const float*)d_in[4];
    float* out = (float*)d_out;

    __nv_bfloat16 *xh, *xl, *wqh, *wql, *woh, *wol, *ah, *al;
    cudaGetSymbolAddress((void**)&xh,  g_xh);
    cudaGetSymbolAddress((void**)&xl,  g_xl);
    cudaGetSymbolAddress((void**)&wqh, g_wqh);
    cudaGetSymbolAddress((void**)&wql, g_wql);
    cudaGetSymbolAddress((void**)&woh, g_woh);
    cudaGetSymbolAddress((void**)&wol, g_wol);
    cudaGetSymbolAddress((void**)&ah,  g_ah);
    cudaGetSymbolAddress((void**)&al,  g_al);

    cudaFuncSetAttribute((const void*)gemm_mma<true, 128>,
                         cudaFuncAttributeMaxDynamicSharedMemorySize, GEMM_SMEM);
    cudaFuncSetAttribute((const void*)gemm_mma<false, 64>,
                         cudaFuncAttributeMaxDynamicSharedMemorySize, GEMM_SMEM);
    cudaFuncSetAttribute(flash_mma, cudaFuncAttributeMaxDynamicSharedMemorySize, FLASH_SMEM);

    // 0) all fp32 -> bf16 hi/lo splits in one vectorized launch
    split_all<<<(NSPLIT4 + 255) / 256, 256>>>(x, w_qkv, w_out);

    // 1) QKV GEMM (128M tiles) -> per-head bf16 hi/lo q/k/v (q pre-scaled)
    gemm_mma<true, 128><<<dim3(QKV_N / 128, M_TOT / 128), 256, GEMM_SMEM>>>(
        xh, xl, wqh, wql, b_qkv, nullptr, QKV_N, DIM);

    // 2) flash attention (HMMA, log2-domain softmax) -> g_ah/g_al
    flash_mma<<<dim3(SEQ / 128, B_SZ * HEADS), 256, FLASH_SMEM>>>();

    // 3) out projection (64M tiles: finer grid, less wave tail) -> d_out
    gemm_mma<false, 64><<<dim3(DIM / 128, M_TOT / 64), 256, GEMM_SMEM>>>(
        ah, al, woh, wol, b_out, out, DIM, DIM);
}